// round 2
// baseline (speedup 1.0000x reference)
#include <cuda_runtime.h>
#include <cuda_bf16.h>

// Problem constants
#define BATCH   4
#define SEQ     2048
#define DM      1024
#define NHEADS  16
#define HD      64
#define TOKENS  (BATCH * SEQ)          // 8192
#define QKV_N   (3 * DM)               // 3072

// Scratch (device globals — no allocation allowed)
__device__ float g_qkv [TOKENS * QKV_N];   // [8192, 3072] row-major
__device__ float g_attn[TOKENS * DM];      // [8192, 1024] row-major

// ---------------------------------------------------------------------------
// SGEMM: C[M,N] = A[M,K] @ B[K,N], all row-major, fp32.
// BM=BN=128, BK=16, 256 threads, 8x8 per-thread tile.
// Requires M%128==0, N%128==0, K%16==0 (true for all our shapes).
// ---------------------------------------------------------------------------
#define GBM 128
#define GBN 128
#define GBK 16
#define GTM 8
#define GTN 8

__global__ __launch_bounds__(256, 2)
void sgemm_kernel(const float* __restrict__ A, const float* __restrict__ B,
                  float* __restrict__ C, int M, int N, int K)
{
    __shared__ float As[GBK][GBM];     // transposed A tile
    __shared__ float Bs[GBK][GBN];

    const int tid  = threadIdx.x;
    const int ty   = tid >> 4;         // 0..15
    const int tx   = tid & 15;         // 0..15
    const int row0 = blockIdx.y * GBM;
    const int col0 = blockIdx.x * GBN;

    float acc[GTM][GTN];
    #pragma unroll
    for (int i = 0; i < GTM; i++)
        #pragma unroll
        for (int j = 0; j < GTN; j++) acc[i][j] = 0.0f;

    for (int k0 = 0; k0 < K; k0 += GBK) {
        // Load A tile (128x16) and B tile (16x128), 512 float4 each total
        #pragma unroll
        for (int l = 0; l < 2; l++) {
            int idx = tid + l * 256;
            int ar = idx >> 2;                   // 0..127
            int ac = (idx & 3) << 2;             // 0,4,8,12
            float4 av = *(const float4*)&A[(size_t)(row0 + ar) * K + k0 + ac];
            As[ac + 0][ar] = av.x;
            As[ac + 1][ar] = av.y;
            As[ac + 2][ar] = av.z;
            As[ac + 3][ar] = av.w;
            int br = idx >> 5;                   // 0..15
            int bc = (idx & 31) << 2;            // 0..124
            *(float4*)&Bs[br][bc] = *(const float4*)&B[(size_t)(k0 + br) * N + col0 + bc];
        }
        __syncthreads();

        #pragma unroll
        for (int kk = 0; kk < GBK; kk++) {
            float ra[GTM], rb[GTN];
            #pragma unroll
            for (int i = 0; i < GTM; i++) ra[i] = As[kk][ty * GTM + i];
            #pragma unroll
            for (int j = 0; j < GTN; j++) rb[j] = Bs[kk][tx * GTN + j];
            #pragma unroll
            for (int i = 0; i < GTM; i++)
                #pragma unroll
                for (int j = 0; j < GTN; j++)
                    acc[i][j] += ra[i] * rb[j];
        }
        __syncthreads();
    }

    #pragma unroll
    for (int i = 0; i < GTM; i++) {
        #pragma unroll
        for (int j = 0; j < GTN; j += 4) {
            float4 v = make_float4(acc[i][j], acc[i][j+1], acc[i][j+2], acc[i][j+3]);
            *(float4*)&C[(size_t)(row0 + ty * GTM + i) * N + col0 + tx * GTN + j] = v;
        }
    }
}

// ---------------------------------------------------------------------------
// Flash attention (fp32, causal). One block = one (b, h, 64-row q tile).
// 256 threads as 16x16; each thread owns a 4x4 tile of the 64x64 score block
// (rows ty*4+i, cols tx*4+j) and a 4x4 tile of the output accumulator.
// Online softmax; k-tiles iterate only up to the causal diagonal.
// ---------------------------------------------------------------------------
#define FBM 64
#define FBN 64
#define KP  68   // padded stride for transposed K / P tiles (multiple of 4)

extern __shared__ float fa_smem[];

__global__ __launch_bounds__(256)
void flash_attn_kernel(const float* __restrict__ qkv, float* __restrict__ attn)
{
    const int qtile = blockIdx.x;     // 0..31
    const int h     = blockIdx.y;     // 0..15
    const int b     = blockIdx.z;     // 0..3

    float* Qs = fa_smem;              // [64][64]
    float* Ks = Qs + 64 * 64;         // [64][KP]  Ks[dd][kn] (transposed)
    float* Vs = Ks + 64 * KP;         // [64][64]  Vs[kn][dd]
    float* Ps = Vs + 64 * 64;         // [64][KP]

    const int tid = threadIdx.x;
    const int ty  = tid >> 4;
    const int tx  = tid & 15;
    const float scale = 0.125f;       // 1/sqrt(64)

    const size_t rowstride = (size_t)QKV_N;  // 3072
    const float* qbase = qkv + (size_t)b * SEQ * QKV_N + h * HD;          // q cols
    const float* kbase = qbase + DM;                                      // k cols
    const float* vbase = qbase + 2 * DM;                                  // v cols

    const int q0 = qtile * FBM;

    // Load Q tile [64 rows x 64 cols] via float4 (1024 float4, 4 per thread)
    #pragma unroll
    for (int l = 0; l < 4; l++) {
        int idx = tid + l * 256;
        int r = idx >> 4;              // 0..63
        int c = (idx & 15) << 2;       // 0..60
        float4 v = *(const float4*)&qbase[(size_t)(q0 + r) * rowstride + c];
        *(float4*)&Qs[r * 64 + c] = v;
    }

    float m_i[4], l_i[4], acc[4][4];
    #pragma unroll
    for (int i = 0; i < 4; i++) {
        m_i[i] = -1e30f; l_i[i] = 0.0f;
        #pragma unroll
        for (int j = 0; j < 4; j++) acc[i][j] = 0.0f;
    }

    for (int kt = 0; kt <= qtile; kt++) {
        const int k0 = kt * FBN;
        __syncthreads();   // prior iter's reads of Ks/Vs/Ps done; Q load fenced on first iter

        // Load K (transposed into Ks[dd][kn]) and V (Vs[kn][dd])
        #pragma unroll
        for (int l = 0; l < 4; l++) {
            int idx = tid + l * 256;
            int r = idx >> 4;          // key row in tile (kn)
            int c = (idx & 15) << 2;   // dd
            float4 kv = *(const float4*)&kbase[(size_t)(k0 + r) * rowstride + c];
            Ks[(c + 0) * KP + r] = kv.x;
            Ks[(c + 1) * KP + r] = kv.y;
            Ks[(c + 2) * KP + r] = kv.z;
            Ks[(c + 3) * KP + r] = kv.w;
            float4 vv = *(const float4*)&vbase[(size_t)(k0 + r) * rowstride + c];
            *(float4*)&Vs[r * 64 + c] = vv;
        }
        __syncthreads();

        // S = Q @ K^T
        float s[4][4];
        #pragma unroll
        for (int i = 0; i < 4; i++)
            #pragma unroll
            for (int j = 0; j < 4; j++) s[i][j] = 0.0f;

        #pragma unroll 8
        for (int dd = 0; dd < 64; dd++) {
            float a[4];
            #pragma unroll
            for (int i = 0; i < 4; i++) a[i] = Qs[(ty * 4 + i) * 64 + dd];
            float4 bv = *(const float4*)&Ks[dd * KP + tx * 4];
            float bb[4] = {bv.x, bv.y, bv.z, bv.w};
            #pragma unroll
            for (int i = 0; i < 4; i++)
                #pragma unroll
                for (int j = 0; j < 4; j++)
                    s[i][j] += a[i] * bb[j];
        }

        // scale + causal mask
        if (kt == qtile) {
            #pragma unroll
            for (int i = 0; i < 4; i++) {
                int qg = q0 + ty * 4 + i;
                #pragma unroll
                for (int j = 0; j < 4; j++) {
                    int kg = k0 + tx * 4 + j;
                    s[i][j] = (kg > qg) ? -1e30f : s[i][j] * scale;
                }
            }
        } else {
            #pragma unroll
            for (int i = 0; i < 4; i++)
                #pragma unroll
                for (int j = 0; j < 4; j++) s[i][j] *= scale;
        }

        // row max across the 16 lanes sharing a row group (width-16 shfl)
        float rmax[4];
        #pragma unroll
        for (int i = 0; i < 4; i++) {
            float m = fmaxf(fmaxf(s[i][0], s[i][1]), fmaxf(s[i][2], s[i][3]));
            #pragma unroll
            for (int off = 8; off >= 1; off >>= 1)
                m = fmaxf(m, __shfl_xor_sync(0xffffffffu, m, off, 16));
            rmax[i] = m;
        }

        float p[4][4], rsum[4];
        #pragma unroll
        for (int i = 0; i < 4; i++) {
            float m_new = fmaxf(m_i[i], rmax[i]);
            float alpha = __expf(m_i[i] - m_new);
            float rs = 0.0f;
            #pragma unroll
            for (int j = 0; j < 4; j++) {
                p[i][j] = __expf(s[i][j] - m_new);
                rs += p[i][j];
            }
            #pragma unroll
            for (int off = 8; off >= 1; off >>= 1)
                rs += __shfl_xor_sync(0xffffffffu, rs, off, 16);
            rsum[i] = rs;
            l_i[i] = l_i[i] * alpha + rs;
            m_i[i] = m_new;
            #pragma unroll
            for (int j = 0; j < 4; j++) acc[i][j] *= alpha;
        }

        // store P to smem
        #pragma unroll
        for (int i = 0; i < 4; i++) {
            *(float4*)&Ps[(ty * 4 + i) * KP + tx * 4] =
                make_float4(p[i][0], p[i][1], p[i][2], p[i][3]);
        }
        __syncthreads();

        // O += P @ V
        #pragma unroll 8
        for (int k = 0; k < 64; k++) {
            float a[4];
            #pragma unroll
            for (int i = 0; i < 4; i++) a[i] = Ps[(ty * 4 + i) * KP + k];
            float4 bv = *(const float4*)&Vs[k * 64 + tx * 4];
            float bb[4] = {bv.x, bv.y, bv.z, bv.w};
            #pragma unroll
            for (int i = 0; i < 4; i++)
                #pragma unroll
                for (int j = 0; j < 4; j++)
                    acc[i][j] += a[i] * bb[j];
        }
    }

    // epilogue: divide by l, write to attn buffer [B,S,H*HD]
    #pragma unroll
    for (int i = 0; i < 4; i++) {
        float inv = 1.0f / l_i[i];
        float4 v = make_float4(acc[i][0] * inv, acc[i][1] * inv,
                               acc[i][2] * inv, acc[i][3] * inv);
        size_t row = (size_t)b * SEQ + q0 + ty * 4 + i;
        *(float4*)&attn[row * DM + h * HD + tx * 4] = v;
    }
}

// ---------------------------------------------------------------------------
// Launch
// ---------------------------------------------------------------------------
extern "C" void kernel_launch(void* const* d_in, const int* in_sizes, int n_in,
                              void* d_out, int out_size)
{
    const float* x     = (const float*)d_in[0];   // [4,2048,1024]
    const float* w_qkv = (const float*)d_in[1];   // [1024,3072]
    const float* w_out = (const float*)d_in[2];   // [1024,1024]
    float* out = (float*)d_out;                   // [4,2048,1024]

    float* qkv;  cudaGetSymbolAddress((void**)&qkv,  g_qkv);
    float* attn; cudaGetSymbolAddress((void**)&attn, g_attn);

    // 1) QKV projection: [8192,1024] @ [1024,3072]
    {
        dim3 grid(QKV_N / GBN, TOKENS / GBM);   // (24, 64)
        sgemm_kernel<<<grid, 256>>>(x, w_qkv, qkv, TOKENS, QKV_N, DM);
    }

    // 2) Flash attention
    {
        const int smem_bytes = (64*64 + 64*KP + 64*64 + 64*KP) * (int)sizeof(float);
        cudaFuncSetAttribute(flash_attn_kernel,
                             cudaFuncAttributeMaxDynamicSharedMemorySize, smem_bytes);
        dim3 grid(SEQ / FBM, NHEADS, BATCH);    // (32, 16, 4)
        flash_attn_kernel<<<grid, 256, smem_bytes>>>(qkv, attn);
    }

    // 3) Output projection: [8192,1024] @ [1024,1024]
    {
        dim3 grid(DM / GBN, TOKENS / GBM);      // (8, 64)
        sgemm_kernel<<<grid, 256>>>(attn, w_out, out, TOKENS, DM, DM);
    }
}

// round 4
// speedup vs baseline: 1.4320x; 1.4320x over previous
#include <cuda_runtime.h>
#include <cuda_bf16.h>
#include <cstdint>

// Problem constants
#define BATCH   4
#define SEQ     2048
#define DM      1024
#define NHEADS  16
#define HD      64
#define TOKENS  (BATCH * SEQ)          // 8192
#define QKV_N   (3 * DM)               // 3072
#define KSPLIT  (3 * DM)               // expanded K' = 3072

// Scratch (device globals — no allocation allowed)
__device__ float g_qkv [(size_t)TOKENS * QKV_N];           // [8192, 3072] fp32
__device__ float g_attn[(size_t)TOKENS * DM];              // [8192, 1024] fp32
__device__ __nv_bfloat16 g_ax   [(size_t)TOKENS * KSPLIT]; // x split:     [Ah|Ah|Al]
__device__ __nv_bfloat16 g_bqkv [(size_t)QKV_N  * KSPLIT]; // w_qkv^T:     [Bh|Bl|Bh]
__device__ __nv_bfloat16 g_aattn[(size_t)TOKENS * KSPLIT]; // attn split
__device__ __nv_bfloat16 g_bout [(size_t)DM     * KSPLIT]; // w_out^T split

// ---------------------------------------------------------------------------
// Helpers
// ---------------------------------------------------------------------------
__device__ __forceinline__ uint32_t smem_u32(const void* p) {
    uint32_t a;
    asm("{ .reg .u64 t; cvta.to.shared.u64 t, %1; cvt.u32.u64 %0, t; }" : "=r"(a) : "l"(p));
    return a;
}

__device__ __forceinline__ void split_bf16(float v, __nv_bfloat16& h, __nv_bfloat16& l) {
    h = __float2bfloat16(v);
    l = __float2bfloat16(v - __bfloat162float(h));
}

#define MMA_BF16(d, a, b) \
    asm volatile("mma.sync.aligned.m16n8k16.row.col.f32.bf16.bf16.f32 " \
        "{%0,%1,%2,%3}, {%4,%5,%6,%7}, {%8,%9}, {%0,%1,%2,%3};" \
        : "+f"((d)[0]), "+f"((d)[1]), "+f"((d)[2]), "+f"((d)[3]) \
        : "r"((a)[0]), "r"((a)[1]), "r"((a)[2]), "r"((a)[3]), \
          "r"((b)[0]), "r"((b)[1]))

// ---------------------------------------------------------------------------
// Split conversion kernels (fp32 -> [hi|hi|lo] / transposed [hi|lo|hi])
// ---------------------------------------------------------------------------
__global__ __launch_bounds__(256)
void conv_split_kernel(const float* __restrict__ in, __nv_bfloat16* __restrict__ out)
{
    int t  = blockIdx.x * 256 + threadIdx.x;
    int r  = t >> 8;
    int c4 = (t & 255) << 2;
    float4 v = *(const float4*)&in[(size_t)r * DM + c4];
    __nv_bfloat16 h0,h1,h2,h3,l0,l1,l2,l3;
    split_bf16(v.x,h0,l0); split_bf16(v.y,h1,l1);
    split_bf16(v.z,h2,l2); split_bf16(v.w,h3,l3);
    __nv_bfloat162 hA = __halves2bfloat162(h0,h1), hB = __halves2bfloat162(h2,h3);
    __nv_bfloat162 lA = __halves2bfloat162(l0,l1), lB = __halves2bfloat162(l2,l3);
    __nv_bfloat162* o = (__nv_bfloat162*)(out + (size_t)r * KSPLIT + c4);
    o[0] = hA; o[1] = hB;
    o[DM/2] = hA; o[DM/2 + 1] = hB;
    o[DM]   = lA; o[DM + 1]   = lB;
}

__global__ __launch_bounds__(256)
void conv_wT_kernel(const float* __restrict__ w, __nv_bfloat16* __restrict__ out, int N)
{
    __shared__ float s[32][33];
    int tx = threadIdx.x & 31, ty = threadIdx.x >> 5;
    int n0 = blockIdx.x * 32, k0 = blockIdx.y * 32;
    #pragma unroll
    for (int i = 0; i < 4; i++)
        s[ty + 8*i][tx] = w[(size_t)(k0 + ty + 8*i) * N + n0 + tx];
    __syncthreads();
    #pragma unroll
    for (int i = 0; i < 4; i++) {
        int n = n0 + ty + 8*i;
        int k = k0 + tx;
        float v = s[tx][ty + 8*i];
        __nv_bfloat16 h, l; split_bf16(v, h, l);
        __nv_bfloat16* o = out + (size_t)n * KSPLIT;
        o[k] = h; o[DM + k] = l; o[2*DM + k] = h;
    }
}

// ---------------------------------------------------------------------------
// HMMA split GEMM: C[M, N] = A'[M, 3072] @ B'[N, 3072]^T  (fp32 accumulate)
// BM=BN=128, BK=32; 256 threads = 8 warps (4x2), warp tile 32x64.
// cp.async double-buffered; smem row stride 40 bf16 (80B) -> conflict-free
// fragment loads. mma.sync m16n8k16 bf16 (portable PTX, no sm_103a features).
// ---------------------------------------------------------------------------
#define BM 128
#define BN 128
#define BK 32
#define SSTRIDE 40    // bf16 elements per smem row (64B data + 16B pad)

__global__ __launch_bounds__(256, 2)
void hmma_split_gemm(const __nv_bfloat16* __restrict__ A,
                     const __nv_bfloat16* __restrict__ B,
                     float* __restrict__ C, int N)
{
    __shared__ __nv_bfloat16 sA[2][BM * SSTRIDE];
    __shared__ __nv_bfloat16 sB[2][BN * SSTRIDE];

    const int tid  = threadIdx.x;
    const int wid  = tid >> 5, lane = tid & 31;
    const int g    = lane >> 2;        // 0..7
    const int tig  = lane & 3;         // 0..3
    const int wm   = (wid >> 1) << 5;  // 0,32,64,96
    const int wn   = (wid & 1) << 6;   // 0,64

    const int row0 = blockIdx.y * BM, col0 = blockIdx.x * BN;
    const char* Ab = (const char*)(A + (size_t)row0 * KSPLIT);
    const char* Bb = (const char*)(B + (size_t)col0 * KSPLIT);

    const uint32_t sA0 = smem_u32(sA);
    const uint32_t sB0 = smem_u32(sB);

    float acc[2][8][4];
    #pragma unroll
    for (int mi = 0; mi < 2; mi++)
        #pragma unroll
        for (int ni = 0; ni < 8; ni++)
            #pragma unroll
            for (int q = 0; q < 4; q++) acc[mi][ni][q] = 0.0f;

#define ISSUE_TILE(buf, kt) do {                                                  \
    size_t kb = (size_t)(kt) * (BK * 2);                                          \
    _Pragma("unroll")                                                             \
    for (int i = 0; i < 2; i++) {                                                 \
        int cch = tid + i * 256;                                                  \
        int rr  = cch >> 2, c16 = (cch & 3) << 4;                                 \
        uint32_t sa = sA0 + (uint32_t)(buf) * (BM * SSTRIDE * 2)                  \
                          + (uint32_t)rr * (SSTRIDE * 2) + c16;                   \
        const char* ga = Ab + (size_t)rr * (KSPLIT * 2) + kb + c16;               \
        asm volatile("cp.async.cg.shared.global [%0], [%1], 16;"                  \
                     :: "r"(sa), "l"(ga));                                        \
        uint32_t sb = sB0 + (uint32_t)(buf) * (BN * SSTRIDE * 2)                  \
                          + (uint32_t)rr * (SSTRIDE * 2) + c16;                   \
        const char* gb = Bb + (size_t)rr * (KSPLIT * 2) + kb + c16;               \
        asm volatile("cp.async.cg.shared.global [%0], [%1], 16;"                  \
                     :: "r"(sb), "l"(gb));                                        \
    }                                                                             \
} while (0)

    ISSUE_TILE(0, 0);
    asm volatile("cp.async.commit_group;" ::: "memory");

    const int nk = KSPLIT / BK;   // 96
    #pragma unroll 1
    for (int kt = 0; kt < nk; kt++) {
        const int buf = kt & 1;
        if (kt + 1 < nk) {
            ISSUE_TILE(buf ^ 1, kt + 1);
            asm volatile("cp.async.commit_group;" ::: "memory");
            asm volatile("cp.async.wait_group 1;" ::: "memory");
        } else {
            asm volatile("cp.async.wait_group 0;" ::: "memory");
        }
        __syncthreads();

        const __nv_bfloat16* As = sA[buf];
        const __nv_bfloat16* Bs = sB[buf];

        #pragma unroll
        for (int ks = 0; ks < 2; ks++) {
            const int k0 = ks * 16 + 2 * tig;

            uint32_t af[2][4];
            #pragma unroll
            for (int mi = 0; mi < 2; mi++) {
                int rA = wm + mi * 16 + g;
                af[mi][0] = *(const uint32_t*)&As[rA * SSTRIDE + k0];
                af[mi][1] = *(const uint32_t*)&As[(rA + 8) * SSTRIDE + k0];
                af[mi][2] = *(const uint32_t*)&As[rA * SSTRIDE + k0 + 8];
                af[mi][3] = *(const uint32_t*)&As[(rA + 8) * SSTRIDE + k0 + 8];
            }
            uint32_t bfr[8][2];
            #pragma unroll
            for (int ni = 0; ni < 8; ni++) {
                int rB = wn + ni * 8 + g;
                bfr[ni][0] = *(const uint32_t*)&Bs[rB * SSTRIDE + k0];
                bfr[ni][1] = *(const uint32_t*)&Bs[rB * SSTRIDE + k0 + 8];
            }
            #pragma unroll
            for (int mi = 0; mi < 2; mi++)
                #pragma unroll
                for (int ni = 0; ni < 8; ni++)
                    MMA_BF16(acc[mi][ni], af[mi], bfr[ni]);
        }
        __syncthreads();
    }
#undef ISSUE_TILE

    // Epilogue: each thread owns rows (wm+mi*16+g, +8), cols (wn+ni*8+2*tig,+1)
    #pragma unroll
    for (int mi = 0; mi < 2; mi++) {
        #pragma unroll
        for (int ni = 0; ni < 8; ni++) {
            int row = row0 + wm + mi * 16 + g;
            int col = col0 + wn + ni * 8 + 2 * tig;
            float2 v0 = make_float2(acc[mi][ni][0], acc[mi][ni][1]);
            float2 v1 = make_float2(acc[mi][ni][2], acc[mi][ni][3]);
            *(float2*)&C[(size_t)row * N + col] = v0;
            *(float2*)&C[(size_t)(row + 8) * N + col] = v1;
        }
    }
}

// ---------------------------------------------------------------------------
// Flash attention (fp32, causal) — unchanged from round 2 (known good)
// ---------------------------------------------------------------------------
#define FBM 64
#define FBN 64
#define KP  68

extern __shared__ float fa_smem[];

__global__ __launch_bounds__(256)
void flash_attn_kernel(const float* __restrict__ qkv, float* __restrict__ attn)
{
    const int qtile = blockIdx.x;
    const int h     = blockIdx.y;
    const int b     = blockIdx.z;

    float* Qs = fa_smem;
    float* Ks = Qs + 64 * 64;
    float* Vs = Ks + 64 * KP;
    float* Ps = Vs + 64 * 64;

    const int tid = threadIdx.x;
    const int ty  = tid >> 4;
    const int tx  = tid & 15;
    const float scale = 0.125f;

    const size_t rowstride = (size_t)QKV_N;
    const float* qbase = qkv + (size_t)b * SEQ * QKV_N + h * HD;
    const float* kbase = qbase + DM;
    const float* vbase = qbase + 2 * DM;

    const int q0 = qtile * FBM;

    #pragma unroll
    for (int l = 0; l < 4; l++) {
        int idx = tid + l * 256;
        int r = idx >> 4;
        int c = (idx & 15) << 2;
        float4 v = *(const float4*)&qbase[(size_t)(q0 + r) * rowstride + c];
        *(float4*)&Qs[r * 64 + c] = v;
    }

    float m_i[4], l_i[4], acc[4][4];
    #pragma unroll
    for (int i = 0; i < 4; i++) {
        m_i[i] = -1e30f; l_i[i] = 0.0f;
        #pragma unroll
        for (int j = 0; j < 4; j++) acc[i][j] = 0.0f;
    }

    for (int kt = 0; kt <= qtile; kt++) {
        const int k0 = kt * FBN;
        __syncthreads();

        #pragma unroll
        for (int l = 0; l < 4; l++) {
            int idx = tid + l * 256;
            int r = idx >> 4;
            int c = (idx & 15) << 2;
            float4 kv = *(const float4*)&kbase[(size_t)(k0 + r) * rowstride + c];
            Ks[(c + 0) * KP + r] = kv.x;
            Ks[(c + 1) * KP + r] = kv.y;
            Ks[(c + 2) * KP + r] = kv.z;
            Ks[(c + 3) * KP + r] = kv.w;
            float4 vv = *(const float4*)&vbase[(size_t)(k0 + r) * rowstride + c];
            *(float4*)&Vs[r * 64 + c] = vv;
        }
        __syncthreads();

        float s[4][4];
        #pragma unroll
        for (int i = 0; i < 4; i++)
            #pragma unroll
            for (int j = 0; j < 4; j++) s[i][j] = 0.0f;

        #pragma unroll 8
        for (int dd = 0; dd < 64; dd++) {
            float a[4];
            #pragma unroll
            for (int i = 0; i < 4; i++) a[i] = Qs[(ty * 4 + i) * 64 + dd];
            float4 bv = *(const float4*)&Ks[dd * KP + tx * 4];
            float bb[4] = {bv.x, bv.y, bv.z, bv.w};
            #pragma unroll
            for (int i = 0; i < 4; i++)
                #pragma unroll
                for (int j = 0; j < 4; j++)
                    s[i][j] += a[i] * bb[j];
        }

        if (kt == qtile) {
            #pragma unroll
            for (int i = 0; i < 4; i++) {
                int qg = q0 + ty * 4 + i;
                #pragma unroll
                for (int j = 0; j < 4; j++) {
                    int kg = k0 + tx * 4 + j;
                    s[i][j] = (kg > qg) ? -1e30f : s[i][j] * scale;
                }
            }
        } else {
            #pragma unroll
            for (int i = 0; i < 4; i++)
                #pragma unroll
                for (int j = 0; j < 4; j++) s[i][j] *= scale;
        }

        float rmax[4];
        #pragma unroll
        for (int i = 0; i < 4; i++) {
            float m = fmaxf(fmaxf(s[i][0], s[i][1]), fmaxf(s[i][2], s[i][3]));
            #pragma unroll
            for (int off = 8; off >= 1; off >>= 1)
                m = fmaxf(m, __shfl_xor_sync(0xffffffffu, m, off, 16));
            rmax[i] = m;
        }

        float p[4][4];
        #pragma unroll
        for (int i = 0; i < 4; i++) {
            float m_new = fmaxf(m_i[i], rmax[i]);
            float alpha = __expf(m_i[i] - m_new);
            float rs = 0.0f;
            #pragma unroll
            for (int j = 0; j < 4; j++) {
                p[i][j] = __expf(s[i][j] - m_new);
                rs += p[i][j];
            }
            #pragma unroll
            for (int off = 8; off >= 1; off >>= 1)
                rs += __shfl_xor_sync(0xffffffffu, rs, off, 16);
            l_i[i] = l_i[i] * alpha + rs;
            m_i[i] = m_new;
            #pragma unroll
            for (int j = 0; j < 4; j++) acc[i][j] *= alpha;
        }

        #pragma unroll
        for (int i = 0; i < 4; i++) {
            *(float4*)&Ps[(ty * 4 + i) * KP + tx * 4] =
                make_float4(p[i][0], p[i][1], p[i][2], p[i][3]);
        }
        __syncthreads();

        #pragma unroll 8
        for (int k = 0; k < 64; k++) {
            float a[4];
            #pragma unroll
            for (int i = 0; i < 4; i++) a[i] = Ps[(ty * 4 + i) * KP + k];
            float4 bv = *(const float4*)&Vs[k * 64 + tx * 4];
            float bb[4] = {bv.x, bv.y, bv.z, bv.w};
            #pragma unroll
            for (int i = 0; i < 4; i++)
                #pragma unroll
                for (int j = 0; j < 4; j++)
                    acc[i][j] += a[i] * bb[j];
        }
    }

    #pragma unroll
    for (int i = 0; i < 4; i++) {
        float inv = 1.0f / l_i[i];
        float4 v = make_float4(acc[i][0] * inv, acc[i][1] * inv,
                               acc[i][2] * inv, acc[i][3] * inv);
        size_t row = (size_t)b * SEQ + q0 + ty * 4 + i;
        *(float4*)&attn[row * DM + h * HD + tx * 4] = v;
    }
}

// ---------------------------------------------------------------------------
// Launch
// ---------------------------------------------------------------------------
extern "C" void kernel_launch(void* const* d_in, const int* in_sizes, int n_in,
                              void* d_out, int out_size)
{
    const float* x     = (const float*)d_in[0];   // [4,2048,1024]
    const float* w_qkv = (const float*)d_in[1];   // [1024,3072]
    const float* w_out = (const float*)d_in[2];   // [1024,1024]
    float* out = (float*)d_out;

    float* qkv;  cudaGetSymbolAddress((void**)&qkv,  g_qkv);
    float* attn; cudaGetSymbolAddress((void**)&attn, g_attn);
    __nv_bfloat16 *ax, *bqkv, *aattn, *bout;
    cudaGetSymbolAddress((void**)&ax,    g_ax);
    cudaGetSymbolAddress((void**)&bqkv,  g_bqkv);
    cudaGetSymbolAddress((void**)&aattn, g_aattn);
    cudaGetSymbolAddress((void**)&bout,  g_bout);

    const int fa_smem_bytes = (64*64 + 64*KP + 64*64 + 64*KP) * (int)sizeof(float);
    cudaFuncSetAttribute(flash_attn_kernel,
                         cudaFuncAttributeMaxDynamicSharedMemorySize, fa_smem_bytes);

    // 1) split conversions for QKV GEMM
    conv_split_kernel<<<TOKENS, 256>>>(x, ax);
    conv_wT_kernel<<<dim3(QKV_N / 32, DM / 32), 256>>>(w_qkv, bqkv, QKV_N);

    // 2) QKV projection: [8192,3072] = ax @ bqkv^T (HMMA bf16 split)
    hmma_split_gemm<<<dim3(QKV_N / BN, TOKENS / BM), 256>>>(ax, bqkv, qkv, QKV_N);

    // 3) Flash attention (fp32)
    flash_attn_kernel<<<dim3(SEQ / FBM, NHEADS, BATCH), 256, fa_smem_bytes>>>(qkv, attn);

    // 4) split conversions for output projection
    conv_split_kernel<<<TOKENS, 256>>>(attn, aattn);
    conv_wT_kernel<<<dim3(DM / 32, DM / 32), 256>>>(w_out, bout, DM);

    // 5) Output projection: [8192,1024] = aattn @ bout^T (HMMA bf16 split)
    hmma_split_gemm<<<dim3(DM / BN, TOKENS / BM), 256>>>(aattn, bout, out, DM);
}

// round 6
// speedup vs baseline: 1.9902x; 1.3898x over previous
#include <cuda_runtime.h>
#include <cuda_bf16.h>
#include <cstdint>

// Problem constants
#define BATCH   4
#define SEQ     2048
#define DM      1024
#define NHEADS  16
#define HD      64
#define TOKENS  (BATCH * SEQ)          // 8192
#define QKV_N   (3 * DM)               // 3072
#define KSPLIT  (3 * DM)               // expanded K' = 3072
#define BH      (BATCH * NHEADS)       // 64
#define HD3     (3 * HD)               // 192 split head dim

// Scratch (device globals — no allocation allowed)
__device__ float g_qkv [(size_t)TOKENS * QKV_N];            // [8192, 3072] fp32
__device__ __nv_bfloat16 g_ax   [(size_t)TOKENS * KSPLIT];  // x split:  [Ah|Ah|Al]
__device__ __nv_bfloat16 g_bqkv [(size_t)QKV_N  * KSPLIT];  // w_qkv^T:  [Bh|Bl|Bh]
__device__ __nv_bfloat16 g_aattn[(size_t)TOKENS * KSPLIT];  // attn out split [Ah|Ah|Al]
__device__ __nv_bfloat16 g_bout [(size_t)DM     * KSPLIT];  // w_out^T split
__device__ __nv_bfloat16 g_qs  [(size_t)BH * SEQ * HD3];    // Q split [bh][s][Qh|Qh|Ql]
__device__ __nv_bfloat16 g_ks  [(size_t)BH * SEQ * HD3];    // K split [bh][s][Kh|Kl|Kh]
__device__ __nv_bfloat16 g_vth [(size_t)BH * HD * SEQ];     // V^T hi  [bh][d][s]
__device__ __nv_bfloat16 g_vtl [(size_t)BH * HD * SEQ];     // V^T lo  [bh][d][s]

// ---------------------------------------------------------------------------
// Helpers
// ---------------------------------------------------------------------------
__device__ __forceinline__ uint32_t smem_u32(const void* p) {
    uint32_t a;
    asm("{ .reg .u64 t; cvta.to.shared.u64 t, %1; cvt.u32.u64 %0, t; }" : "=r"(a) : "l"(p));
    return a;
}
__device__ __forceinline__ void split_bf16(float v, __nv_bfloat16& h, __nv_bfloat16& l) {
    h = __float2bfloat16(v);
    l = __float2bfloat16(v - __bfloat162float(h));
}
#define MMA_BF16(d, a, b) \
    asm volatile("mma.sync.aligned.m16n8k16.row.col.f32.bf16.bf16.f32 " \
        "{%0,%1,%2,%3}, {%4,%5,%6,%7}, {%8,%9}, {%0,%1,%2,%3};" \
        : "+f"((d)[0]), "+f"((d)[1]), "+f"((d)[2]), "+f"((d)[3]) \
        : "r"((a)[0]), "r"((a)[1]), "r"((a)[2]), "r"((a)[3]), \
          "r"((b)[0]), "r"((b)[1]))

// ---------------------------------------------------------------------------
// Input split conversions (proven in round 4)
// ---------------------------------------------------------------------------
__global__ __launch_bounds__(256)
void conv_split_kernel(const float* __restrict__ in, __nv_bfloat16* __restrict__ out)
{
    int t  = blockIdx.x * 256 + threadIdx.x;
    int r  = t >> 8;
    int c4 = (t & 255) << 2;
    float4 v = *(const float4*)&in[(size_t)r * DM + c4];
    __nv_bfloat16 h0,h1,h2,h3,l0,l1,l2,l3;
    split_bf16(v.x,h0,l0); split_bf16(v.y,h1,l1);
    split_bf16(v.z,h2,l2); split_bf16(v.w,h3,l3);
    __nv_bfloat162 hA = __halves2bfloat162(h0,h1), hB = __halves2bfloat162(h2,h3);
    __nv_bfloat162 lA = __halves2bfloat162(l0,l1), lB = __halves2bfloat162(l2,l3);
    __nv_bfloat162* o = (__nv_bfloat162*)(out + (size_t)r * KSPLIT + c4);
    o[0] = hA; o[1] = hB;
    o[DM/2] = hA; o[DM/2 + 1] = hB;
    o[DM]   = lA; o[DM + 1]   = lB;
}

__global__ __launch_bounds__(256)
void conv_wT_kernel(const float* __restrict__ w, __nv_bfloat16* __restrict__ out, int N)
{
    __shared__ float s[32][33];
    int tx = threadIdx.x & 31, ty = threadIdx.x >> 5;
    int n0 = blockIdx.x * 32, k0 = blockIdx.y * 32;
    #pragma unroll
    for (int i = 0; i < 4; i++)
        s[ty + 8*i][tx] = w[(size_t)(k0 + ty + 8*i) * N + n0 + tx];
    __syncthreads();
    #pragma unroll
    for (int i = 0; i < 4; i++) {
        int n = n0 + ty + 8*i;
        int k = k0 + tx;
        float v = s[tx][ty + 8*i];
        __nv_bfloat16 h, l; split_bf16(v, h, l);
        __nv_bfloat16* o = out + (size_t)n * KSPLIT;
        o[k] = h; o[DM + k] = l; o[2*DM + k] = h;
    }
}

// ---------------------------------------------------------------------------
// qkv fp32 -> attention split layouts. Block = (s-tile 64, h, b).
// ---------------------------------------------------------------------------
__global__ __launch_bounds__(256)
void conv_qkv_split(const float* __restrict__ qkv,
                    __nv_bfloat16* __restrict__ qs, __nv_bfloat16* __restrict__ ks,
                    __nv_bfloat16* __restrict__ vth, __nv_bfloat16* __restrict__ vtl)
{
    __shared__ float vs[64][65];
    const int st = blockIdx.x, h = blockIdx.y, b = blockIdx.z;
    const int bh = b * NHEADS + h;
    const int tid = threadIdx.x;
    const float* base = qkv + ((size_t)b * SEQ + st * 64) * QKV_N + h * HD;

    // Q and K
    #pragma unroll
    for (int i = 0; i < 4; i++) {
        int idx = i * 256 + tid;
        int r = idx >> 4, c4 = (idx & 15) << 2;
        // Q -> [Qh|Qh|Ql]
        {
            float4 v = *(const float4*)(base + (size_t)r * QKV_N + c4);
            __nv_bfloat16 h0,h1,h2,h3,l0,l1,l2,l3;
            split_bf16(v.x,h0,l0); split_bf16(v.y,h1,l1);
            split_bf16(v.z,h2,l2); split_bf16(v.w,h3,l3);
            __nv_bfloat162 hA = __halves2bfloat162(h0,h1), hB = __halves2bfloat162(h2,h3);
            __nv_bfloat162 lA = __halves2bfloat162(l0,l1), lB = __halves2bfloat162(l2,l3);
            __nv_bfloat16* o = qs + ((size_t)bh * SEQ + st * 64 + r) * HD3 + c4;
            *(__nv_bfloat162*)(o)       = hA; *(__nv_bfloat162*)(o + 2)       = hB;
            *(__nv_bfloat162*)(o + 64)  = hA; *(__nv_bfloat162*)(o + 66)      = hB;
            *(__nv_bfloat162*)(o + 128) = lA; *(__nv_bfloat162*)(o + 130)     = lB;
        }
        // K -> [Kh|Kl|Kh]
        {
            float4 v = *(const float4*)(base + DM + (size_t)r * QKV_N + c4);
            __nv_bfloat16 h0,h1,h2,h3,l0,l1,l2,l3;
            split_bf16(v.x,h0,l0); split_bf16(v.y,h1,l1);
            split_bf16(v.z,h2,l2); split_bf16(v.w,h3,l3);
            __nv_bfloat162 hA = __halves2bfloat162(h0,h1), hB = __halves2bfloat162(h2,h3);
            __nv_bfloat162 lA = __halves2bfloat162(l0,l1), lB = __halves2bfloat162(l2,l3);
            __nv_bfloat16* o = ks + ((size_t)bh * SEQ + st * 64 + r) * HD3 + c4;
            *(__nv_bfloat162*)(o)       = hA; *(__nv_bfloat162*)(o + 2)       = hB;
            *(__nv_bfloat162*)(o + 64)  = lA; *(__nv_bfloat162*)(o + 66)      = lB;
            *(__nv_bfloat162*)(o + 128) = hA; *(__nv_bfloat162*)(o + 130)     = hB;
        }
        // V stage to smem
        float4 v = *(const float4*)(base + 2 * DM + (size_t)r * QKV_N + c4);
        vs[r][c4] = v.x; vs[r][c4+1] = v.y; vs[r][c4+2] = v.z; vs[r][c4+3] = v.w;
    }
    __syncthreads();
    // V transposed split write
    #pragma unroll
    for (int i = 0; i < 4; i++) {
        int idx = i * 256 + tid;
        int d = idx >> 4, s4 = (idx & 15) << 2;
        float x0 = vs[s4][d], x1 = vs[s4+1][d], x2 = vs[s4+2][d], x3 = vs[s4+3][d];
        __nv_bfloat16 h0,h1,h2,h3,l0,l1,l2,l3;
        split_bf16(x0,h0,l0); split_bf16(x1,h1,l1);
        split_bf16(x2,h2,l2); split_bf16(x3,h3,l3);
        __nv_bfloat16* oh = vth + ((size_t)bh * HD + d) * SEQ + st * 64 + s4;
        __nv_bfloat16* ol = vtl + ((size_t)bh * HD + d) * SEQ + st * 64 + s4;
        *(__nv_bfloat162*)(oh)     = __halves2bfloat162(h0,h1);
        *(__nv_bfloat162*)(oh + 2) = __halves2bfloat162(h2,h3);
        *(__nv_bfloat162*)(ol)     = __halves2bfloat162(l0,l1);
        *(__nv_bfloat162*)(ol + 2) = __halves2bfloat162(l2,l3);
    }
}

// ---------------------------------------------------------------------------
// HMMA split GEMM (unchanged, proven round 4)
// ---------------------------------------------------------------------------
#define BM 128
#define BN 128
#define BK 32
#define SSTRIDE 40

__global__ __launch_bounds__(256, 2)
void hmma_split_gemm(const __nv_bfloat16* __restrict__ A,
                     const __nv_bfloat16* __restrict__ B,
                     float* __restrict__ C, int N)
{
    __shared__ __nv_bfloat16 sA[2][BM * SSTRIDE];
    __shared__ __nv_bfloat16 sB[2][BN * SSTRIDE];

    const int tid  = threadIdx.x;
    const int wid  = tid >> 5, lane = tid & 31;
    const int g    = lane >> 2;
    const int tig  = lane & 3;
    const int wm   = (wid >> 1) << 5;
    const int wn   = (wid & 1) << 6;

    const int row0 = blockIdx.y * BM, col0 = blockIdx.x * BN;
    const char* Ab = (const char*)(A + (size_t)row0 * KSPLIT);
    const char* Bb = (const char*)(B + (size_t)col0 * KSPLIT);

    const uint32_t sA0 = smem_u32(sA);
    const uint32_t sB0 = smem_u32(sB);

    float acc[2][8][4];
    #pragma unroll
    for (int mi = 0; mi < 2; mi++)
        #pragma unroll
        for (int ni = 0; ni < 8; ni++)
            #pragma unroll
            for (int q = 0; q < 4; q++) acc[mi][ni][q] = 0.0f;

#define ISSUE_TILE(buf, kt) do {                                                  \
    size_t kb = (size_t)(kt) * (BK * 2);                                          \
    _Pragma("unroll")                                                             \
    for (int i = 0; i < 2; i++) {                                                 \
        int cch = tid + i * 256;                                                  \
        int rr  = cch >> 2, c16 = (cch & 3) << 4;                                 \
        uint32_t sa = sA0 + (uint32_t)(buf) * (BM * SSTRIDE * 2)                  \
                          + (uint32_t)rr * (SSTRIDE * 2) + c16;                   \
        const char* ga = Ab + (size_t)rr * (KSPLIT * 2) + kb + c16;               \
        asm volatile("cp.async.cg.shared.global [%0], [%1], 16;"                  \
                     :: "r"(sa), "l"(ga));                                        \
        uint32_t sb = sB0 + (uint32_t)(buf) * (BN * SSTRIDE * 2)                  \
                          + (uint32_t)rr * (SSTRIDE * 2) + c16;                   \
        const char* gb = Bb + (size_t)rr * (KSPLIT * 2) + kb + c16;               \
        asm volatile("cp.async.cg.shared.global [%0], [%1], 16;"                  \
                     :: "r"(sb), "l"(gb));                                        \
    }                                                                             \
} while (0)

    ISSUE_TILE(0, 0);
    asm volatile("cp.async.commit_group;" ::: "memory");

    const int nk = KSPLIT / BK;
    #pragma unroll 1
    for (int kt = 0; kt < nk; kt++) {
        const int buf = kt & 1;
        if (kt + 1 < nk) {
            ISSUE_TILE(buf ^ 1, kt + 1);
            asm volatile("cp.async.commit_group;" ::: "memory");
            asm volatile("cp.async.wait_group 1;" ::: "memory");
        } else {
            asm volatile("cp.async.wait_group 0;" ::: "memory");
        }
        __syncthreads();

        const __nv_bfloat16* As = sA[buf];
        const __nv_bfloat16* Bs = sB[buf];

        #pragma unroll
        for (int ks = 0; ks < 2; ks++) {
            const int k0 = ks * 16 + 2 * tig;
            uint32_t af[2][4];
            #pragma unroll
            for (int mi = 0; mi < 2; mi++) {
                int rA = wm + mi * 16 + g;
                af[mi][0] = *(const uint32_t*)&As[rA * SSTRIDE + k0];
                af[mi][1] = *(const uint32_t*)&As[(rA + 8) * SSTRIDE + k0];
                af[mi][2] = *(const uint32_t*)&As[rA * SSTRIDE + k0 + 8];
                af[mi][3] = *(const uint32_t*)&As[(rA + 8) * SSTRIDE + k0 + 8];
            }
            uint32_t bfr[8][2];
            #pragma unroll
            for (int ni = 0; ni < 8; ni++) {
                int rB = wn + ni * 8 + g;
                bfr[ni][0] = *(const uint32_t*)&Bs[rB * SSTRIDE + k0];
                bfr[ni][1] = *(const uint32_t*)&Bs[rB * SSTRIDE + k0 + 8];
            }
            #pragma unroll
            for (int mi = 0; mi < 2; mi++)
                #pragma unroll
                for (int ni = 0; ni < 8; ni++)
                    MMA_BF16(acc[mi][ni], af[mi], bfr[ni]);
        }
        __syncthreads();
    }
#undef ISSUE_TILE

    #pragma unroll
    for (int mi = 0; mi < 2; mi++) {
        #pragma unroll
        for (int ni = 0; ni < 8; ni++) {
            int row = row0 + wm + mi * 16 + g;
            int col = col0 + wn + ni * 8 + 2 * tig;
            *(float2*)&C[(size_t)row * N + col] = make_float2(acc[mi][ni][0], acc[mi][ni][1]);
            *(float2*)&C[(size_t)(row + 8) * N + col] = make_float2(acc[mi][ni][2], acc[mi][ni][3]);
        }
    }
}

// ---------------------------------------------------------------------------
// HMMA flash attention (split bf16, causal).
// Block = (b, h, 128-row q tile). 256 threads, 8 warps x 16 q-rows.
// S = Q'[128,192] @ K'[64,192]^T ; softmax (warp-local) ; O += P'[.,192] @ V'[64,192]^T
// Output written directly as [Ah|Ah|Al] split into g_aattn.
// ---------------------------------------------------------------------------
#define AST 200   // smem row stride in bf16 (400B): fragment LDS conflict-free

__global__ __launch_bounds__(256, 1)
void hmma_flash_attn(const __nv_bfloat16* __restrict__ qs,
                     const __nv_bfloat16* __restrict__ ks,
                     const __nv_bfloat16* __restrict__ vth,
                     const __nv_bfloat16* __restrict__ vtl,
                     __nv_bfloat16* __restrict__ aout)
{
    extern __shared__ __nv_bfloat16 asm_[];
    __nv_bfloat16* Qs  = asm_;               // [128][AST]
    __nv_bfloat16* Ks  = asm_ + 128 * AST;   // [64][AST]
    __nv_bfloat16* Vts = asm_ + 192 * AST;   // [64][AST]
    __nv_bfloat16* Ps  = asm_ + 256 * AST;   // [128][AST]

    const int tid  = threadIdx.x;
    const int wid  = tid >> 5, lane = tid & 31;
    const int g    = lane >> 2, tig = lane & 3;
    const int wq0  = wid * 16;

    const int qt = (int)(gridDim.x - 1) - (int)blockIdx.x;  // big tiles first
    const int h  = blockIdx.y, b = blockIdx.z;
    const int bh = b * NHEADS + h;
    const int q0 = qt * 128;

    const __nv_bfloat16* qbase = qs  + ((size_t)bh * SEQ + q0) * HD3;
    const __nv_bfloat16* kbase = ks  + (size_t)bh * SEQ * HD3;
    const __nv_bfloat16* vhb   = vth + (size_t)bh * HD * SEQ;
    const __nv_bfloat16* vlb   = vtl + (size_t)bh * HD * SEQ;

    // load Q' tile [128][192]
    #pragma unroll
    for (int i = 0; i < 12; i++) {
        int idx = i * 256 + tid;
        int r = idx / 24, c = (idx % 24) * 8;
        uint4 v = *(const uint4*)(qbase + (size_t)r * HD3 + c);
        *(uint4*)(Qs + r * AST + c) = v;
    }

    float m0 = -1e30f, m1 = -1e30f, l0 = 0.0f, l1 = 0.0f;
    float o[8][4];
    #pragma unroll
    for (int ni = 0; ni < 8; ni++)
        #pragma unroll
        for (int q = 0; q < 4; q++) o[ni][q] = 0.0f;

    const int nkt = 2 * qt + 2;
    #pragma unroll 1
    for (int kt = 0; kt < nkt; kt++) {
        const int k0 = kt * 64;
        __syncthreads();
        // load K' tile [64][192]
        #pragma unroll
        for (int i = 0; i < 6; i++) {
            int idx = i * 256 + tid;
            int r = idx / 24, c = (idx % 24) * 8;
            uint4 v = *(const uint4*)(kbase + (size_t)(k0 + r) * HD3 + c);
            *(uint4*)(Ks + r * AST + c) = v;
        }
        // load V' tile [64 d][192 kn'] = [Vh | Vl | Vh]
        #pragma unroll
        for (int i = 0; i < 2; i++) {
            int idx = i * 256 + tid;
            int d = idx >> 3, s8 = (idx & 7) << 3;
            uint4 vh = *(const uint4*)(vhb + (size_t)d * SEQ + k0 + s8);
            *(uint4*)(Vts + d * AST + s8)       = vh;
            *(uint4*)(Vts + d * AST + 128 + s8) = vh;
            uint4 vl = *(const uint4*)(vlb + (size_t)d * SEQ + k0 + s8);
            *(uint4*)(Vts + d * AST + 64 + s8)  = vl;
        }
        __syncthreads();

        // S = Q' @ K'^T (warp rows [wq0, wq0+16), 64 kn cols)
        float s[8][4];
        #pragma unroll
        for (int ni = 0; ni < 8; ni++)
            #pragma unroll
            for (int q = 0; q < 4; q++) s[ni][q] = 0.0f;

        #pragma unroll
        for (int kss = 0; kss < 12; kss++) {
            const int kk = kss * 16 + 2 * tig;
            uint32_t a[4];
            const int rA = wq0 + g;
            a[0] = *(const uint32_t*)(Qs + rA * AST + kk);
            a[1] = *(const uint32_t*)(Qs + (rA + 8) * AST + kk);
            a[2] = *(const uint32_t*)(Qs + rA * AST + kk + 8);
            a[3] = *(const uint32_t*)(Qs + (rA + 8) * AST + kk + 8);
            #pragma unroll
            for (int ni = 0; ni < 8; ni++) {
                uint32_t bb[2];
                const int rB = ni * 8 + g;
                bb[0] = *(const uint32_t*)(Ks + rB * AST + kk);
                bb[1] = *(const uint32_t*)(Ks + rB * AST + kk + 8);
                MMA_BF16(s[ni], a, bb);
            }
        }

        // scale + causal mask
        const float scale = 0.125f;
        if (kt >= nkt - 2) {
            const int r0 = q0 + wq0 + g, r1 = r0 + 8;
            #pragma unroll
            for (int ni = 0; ni < 8; ni++) {
                const int c = k0 + ni * 8 + 2 * tig;
                s[ni][0] = (c     > r0) ? -1e30f : s[ni][0] * scale;
                s[ni][1] = (c + 1 > r0) ? -1e30f : s[ni][1] * scale;
                s[ni][2] = (c     > r1) ? -1e30f : s[ni][2] * scale;
                s[ni][3] = (c + 1 > r1) ? -1e30f : s[ni][3] * scale;
            }
        } else {
            #pragma unroll
            for (int ni = 0; ni < 8; ni++)
                #pragma unroll
                for (int q = 0; q < 4; q++) s[ni][q] *= scale;
        }

        // warp-local online softmax (rows r0 = wq0+g, r1 = wq0+8+g)
        float rmax0 = -1e30f, rmax1 = -1e30f;
        #pragma unroll
        for (int ni = 0; ni < 8; ni++) {
            rmax0 = fmaxf(rmax0, fmaxf(s[ni][0], s[ni][1]));
            rmax1 = fmaxf(rmax1, fmaxf(s[ni][2], s[ni][3]));
        }
        rmax0 = fmaxf(rmax0, __shfl_xor_sync(0xffffffffu, rmax0, 1));
        rmax0 = fmaxf(rmax0, __shfl_xor_sync(0xffffffffu, rmax0, 2));
        rmax1 = fmaxf(rmax1, __shfl_xor_sync(0xffffffffu, rmax1, 1));
        rmax1 = fmaxf(rmax1, __shfl_xor_sync(0xffffffffu, rmax1, 2));

        const float mn0 = fmaxf(m0, rmax0), mn1 = fmaxf(m1, rmax1);
        const float al0 = __expf(m0 - mn0), al1 = __expf(m1 - mn1);
        float rs0 = 0.0f, rs1 = 0.0f;

        __nv_bfloat16* prow0 = Ps + (wq0 + g) * AST + 2 * tig;
        __nv_bfloat16* prow1 = prow0 + 8 * AST;
        #pragma unroll
        for (int ni = 0; ni < 8; ni++) {
            float p0 = __expf(s[ni][0] - mn0);
            float p1 = __expf(s[ni][1] - mn0);
            float p2 = __expf(s[ni][2] - mn1);
            float p3 = __expf(s[ni][3] - mn1);
            rs0 += p0 + p1; rs1 += p2 + p3;
            __nv_bfloat16 h0,h1,h2,h3,q0b,q1b,q2b,q3b;
            split_bf16(p0,h0,q0b); split_bf16(p1,h1,q1b);
            split_bf16(p2,h2,q2b); split_bf16(p3,h3,q3b);
            __nv_bfloat162 hp01 = __halves2bfloat162(h0,h1);
            __nv_bfloat162 lp01 = __halves2bfloat162(q0b,q1b);
            __nv_bfloat162 hp23 = __halves2bfloat162(h2,h3);
            __nv_bfloat162 lp23 = __halves2bfloat162(q2b,q3b);
            *(__nv_bfloat162*)(prow0 + ni*8)       = hp01;
            *(__nv_bfloat162*)(prow0 + ni*8 + 64)  = hp01;
            *(__nv_bfloat162*)(prow0 + ni*8 + 128) = lp01;
            *(__nv_bfloat162*)(prow1 + ni*8)       = hp23;
            *(__nv_bfloat162*)(prow1 + ni*8 + 64)  = hp23;
            *(__nv_bfloat162*)(prow1 + ni*8 + 128) = lp23;
        }
        rs0 += __shfl_xor_sync(0xffffffffu, rs0, 1);
        rs0 += __shfl_xor_sync(0xffffffffu, rs0, 2);
        rs1 += __shfl_xor_sync(0xffffffffu, rs1, 1);
        rs1 += __shfl_xor_sync(0xffffffffu, rs1, 2);

        l0 = l0 * al0 + rs0; m0 = mn0;
        l1 = l1 * al1 + rs1; m1 = mn1;
        #pragma unroll
        for (int ni = 0; ni < 8; ni++) {
            o[ni][0] *= al0; o[ni][1] *= al0;
            o[ni][2] *= al1; o[ni][3] *= al1;
        }
        __syncwarp();

        // O += P' @ V'^T
        #pragma unroll
        for (int kss = 0; kss < 12; kss++) {
            const int kk = kss * 16 + 2 * tig;
            uint32_t a[4];
            const int rA = wq0 + g;
            a[0] = *(const uint32_t*)(Ps + rA * AST + kk);
            a[1] = *(const uint32_t*)(Ps + (rA + 8) * AST + kk);
            a[2] = *(const uint32_t*)(Ps + rA * AST + kk + 8);
            a[3] = *(const uint32_t*)(Ps + (rA + 8) * AST + kk + 8);
            #pragma unroll
            for (int ni = 0; ni < 8; ni++) {
                uint32_t bb[2];
                const int rB = ni * 8 + g;
                bb[0] = *(const uint32_t*)(Vts + rB * AST + kk);
                bb[1] = *(const uint32_t*)(Vts + rB * AST + kk + 8);
                MMA_BF16(o[ni], a, bb);
            }
        }
    }

    // epilogue: divide by l, split to bf16, write [Ah|Ah|Al] rows of g_aattn
    const float inv0 = 1.0f / l0, inv1 = 1.0f / l1;
    const size_t t0 = ((size_t)b * SEQ + q0 + wq0 + g) * KSPLIT + h * HD;
    const size_t t1 = t0 + (size_t)8 * KSPLIT;
    #pragma unroll
    for (int ni = 0; ni < 8; ni++) {
        const int c = ni * 8 + 2 * tig;
        float f0 = o[ni][0] * inv0, f1 = o[ni][1] * inv0;
        float f2 = o[ni][2] * inv1, f3 = o[ni][3] * inv1;
        __nv_bfloat16 h0,h1,h2,h3,l0b,l1b,l2b,l3b;
        split_bf16(f0,h0,l0b); split_bf16(f1,h1,l1b);
        split_bf16(f2,h2,l2b); split_bf16(f3,h3,l3b);
        __nv_bfloat162 hp01 = __halves2bfloat162(h0,h1), lp01 = __halves2bfloat162(l0b,l1b);
        __nv_bfloat162 hp23 = __halves2bfloat162(h2,h3), lp23 = __halves2bfloat162(l2b,l3b);
        *(__nv_bfloat162*)(aout + t0 + c)          = hp01;
        *(__nv_bfloat162*)(aout + t0 + DM + c)     = hp01;
        *(__nv_bfloat162*)(aout + t0 + 2*DM + c)   = lp01;
        *(__nv_bfloat162*)(aout + t1 + c)          = hp23;
        *(__nv_bfloat162*)(aout + t1 + DM + c)     = hp23;
        *(__nv_bfloat162*)(aout + t1 + 2*DM + c)   = lp23;
    }
}

// ---------------------------------------------------------------------------
// Launch
// ---------------------------------------------------------------------------
extern "C" void kernel_launch(void* const* d_in, const int* in_sizes, int n_in,
                              void* d_out, int out_size)
{
    const float* x     = (const float*)d_in[0];
    const float* w_qkv = (const float*)d_in[1];
    const float* w_out = (const float*)d_in[2];
    float* out = (float*)d_out;

    float* qkv; cudaGetSymbolAddress((void**)&qkv, g_qkv);
    __nv_bfloat16 *ax, *bqkv, *aattn, *bout, *pqs, *pks, *pvth, *pvtl;
    cudaGetSymbolAddress((void**)&ax,    g_ax);
    cudaGetSymbolAddress((void**)&bqkv,  g_bqkv);
    cudaGetSymbolAddress((void**)&aattn, g_aattn);
    cudaGetSymbolAddress((void**)&bout,  g_bout);
    cudaGetSymbolAddress((void**)&pqs,   g_qs);
    cudaGetSymbolAddress((void**)&pks,   g_ks);
    cudaGetSymbolAddress((void**)&pvth,  g_vth);
    cudaGetSymbolAddress((void**)&pvtl,  g_vtl);

    const int fa_smem = 384 * AST * (int)sizeof(__nv_bfloat16);   // 153600 B
    cudaFuncSetAttribute(hmma_flash_attn,
                         cudaFuncAttributeMaxDynamicSharedMemorySize, fa_smem);

    // 1) input splits
    conv_split_kernel<<<TOKENS, 256>>>(x, ax);
    conv_wT_kernel<<<dim3(QKV_N / 32, DM / 32), 256>>>(w_qkv, bqkv, QKV_N);

    // 2) QKV projection (fp32 out)
    hmma_split_gemm<<<dim3(QKV_N / BN, TOKENS / BM), 256>>>(ax, bqkv, qkv, QKV_N);

    // 3) qkv -> attention split layouts
    conv_qkv_split<<<dim3(SEQ / 64, NHEADS, BATCH), 256>>>(qkv, pqs, pks, pvth, pvtl);

    // 4) HMMA flash attention -> split bf16 activations for out-proj
    hmma_flash_attn<<<dim3(SEQ / 128, NHEADS, BATCH), 256, fa_smem>>>(pqs, pks, pvth, pvtl, aattn);

    // 5) output projection
    conv_wT_kernel<<<dim3(DM / 32, DM / 32), 256>>>(w_out, bout, DM);
    hmma_split_gemm<<<dim3(DM / BN, TOKENS / BM), 256>>>(aattn, bout, out, DM);
}

// round 7
// speedup vs baseline: 2.3257x; 1.1686x over previous
#include <cuda_runtime.h>
#include <cuda_bf16.h>
#include <cstdint>

// Problem constants
#define BATCH   4
#define SEQ     2048
#define DM      1024
#define NHEADS  16
#define HD      64
#define TOKENS  (BATCH * SEQ)          // 8192
#define QKV_N   (3 * DM)               // 3072
#define KSPLIT  (3 * DM)               // expanded K' = 3072
#define BH      (BATCH * NHEADS)       // 64
#define HD3     (3 * HD)               // 192 split head dim

// Scratch (device globals — no allocation allowed)
__device__ float g_qkv [(size_t)TOKENS * QKV_N];            // [8192, 3072] fp32
__device__ __nv_bfloat16 g_ax   [(size_t)TOKENS * KSPLIT];  // x split:  [Ah|Ah|Al]
__device__ __nv_bfloat16 g_bqkv [(size_t)QKV_N  * KSPLIT];  // w_qkv^T:  [Bh|Bl|Bh]
__device__ __nv_bfloat16 g_aattn[(size_t)TOKENS * KSPLIT];  // attn out split [Ah|Ah|Al]
__device__ __nv_bfloat16 g_bout [(size_t)DM     * KSPLIT];  // w_out^T split
__device__ __nv_bfloat16 g_qs  [(size_t)BH * SEQ * HD3];    // Q split [bh][s][Qh|Qh|Ql]
__device__ __nv_bfloat16 g_ks  [(size_t)BH * SEQ * HD3];    // K split [bh][s][Kh|Kl|Kh]
__device__ __nv_bfloat16 g_vth [(size_t)BH * HD * SEQ];     // V^T hi  [bh][d][s]
__device__ __nv_bfloat16 g_vtl [(size_t)BH * HD * SEQ];     // V^T lo  [bh][d][s]

// ---------------------------------------------------------------------------
// Helpers
// ---------------------------------------------------------------------------
__device__ __forceinline__ uint32_t smem_u32(const void* p) {
    uint32_t a;
    asm("{ .reg .u64 t; cvta.to.shared.u64 t, %1; cvt.u32.u64 %0, t; }" : "=r"(a) : "l"(p));
    return a;
}
__device__ __forceinline__ void split_bf16(float v, __nv_bfloat16& h, __nv_bfloat16& l) {
    h = __float2bfloat16(v);
    l = __float2bfloat16(v - __bfloat162float(h));
}
#define MMA_BF16(d, a, b) \
    asm volatile("mma.sync.aligned.m16n8k16.row.col.f32.bf16.bf16.f32 " \
        "{%0,%1,%2,%3}, {%4,%5,%6,%7}, {%8,%9}, {%0,%1,%2,%3};" \
        : "+f"((d)[0]), "+f"((d)[1]), "+f"((d)[2]), "+f"((d)[3]) \
        : "r"((a)[0]), "r"((a)[1]), "r"((a)[2]), "r"((a)[3]), \
          "r"((b)[0]), "r"((b)[1]))
#define LDMX4(r, addr) \
    asm volatile("ldmatrix.sync.aligned.m8n8.x4.shared.b16 {%0,%1,%2,%3}, [%4];" \
        : "=r"((r)[0]), "=r"((r)[1]), "=r"((r)[2]), "=r"((r)[3]) : "r"(addr))

// ---------------------------------------------------------------------------
// Input split conversions (proven)
// ---------------------------------------------------------------------------
__global__ __launch_bounds__(256)
void conv_split_kernel(const float* __restrict__ in, __nv_bfloat16* __restrict__ out)
{
    int t  = blockIdx.x * 256 + threadIdx.x;
    int r  = t >> 8;
    int c4 = (t & 255) << 2;
    float4 v = *(const float4*)&in[(size_t)r * DM + c4];
    __nv_bfloat16 h0,h1,h2,h3,l0,l1,l2,l3;
    split_bf16(v.x,h0,l0); split_bf16(v.y,h1,l1);
    split_bf16(v.z,h2,l2); split_bf16(v.w,h3,l3);
    __nv_bfloat162 hA = __halves2bfloat162(h0,h1), hB = __halves2bfloat162(h2,h3);
    __nv_bfloat162 lA = __halves2bfloat162(l0,l1), lB = __halves2bfloat162(l2,l3);
    __nv_bfloat162* o = (__nv_bfloat162*)(out + (size_t)r * KSPLIT + c4);
    o[0] = hA; o[1] = hB;
    o[DM/2] = hA; o[DM/2 + 1] = hB;
    o[DM]   = lA; o[DM + 1]   = lB;
}

__global__ __launch_bounds__(256)
void conv_wT_kernel(const float* __restrict__ w, __nv_bfloat16* __restrict__ out, int N)
{
    __shared__ float s[32][33];
    int tx = threadIdx.x & 31, ty = threadIdx.x >> 5;
    int n0 = blockIdx.x * 32, k0 = blockIdx.y * 32;
    #pragma unroll
    for (int i = 0; i < 4; i++)
        s[ty + 8*i][tx] = w[(size_t)(k0 + ty + 8*i) * N + n0 + tx];
    __syncthreads();
    #pragma unroll
    for (int i = 0; i < 4; i++) {
        int n = n0 + ty + 8*i;
        int k = k0 + tx;
        float v = s[tx][ty + 8*i];
        __nv_bfloat16 h, l; split_bf16(v, h, l);
        __nv_bfloat16* o = out + (size_t)n * KSPLIT;
        o[k] = h; o[DM + k] = l; o[2*DM + k] = h;
    }
}

// ---------------------------------------------------------------------------
// qkv fp32 -> attention split layouts. Block = (s-tile 64, h, b).
// ---------------------------------------------------------------------------
__global__ __launch_bounds__(256)
void conv_qkv_split(const float* __restrict__ qkv,
                    __nv_bfloat16* __restrict__ qs, __nv_bfloat16* __restrict__ ks,
                    __nv_bfloat16* __restrict__ vth, __nv_bfloat16* __restrict__ vtl)
{
    __shared__ float vs[64][65];
    const int st = blockIdx.x, h = blockIdx.y, b = blockIdx.z;
    const int bh = b * NHEADS + h;
    const int tid = threadIdx.x;
    const float* base = qkv + ((size_t)b * SEQ + st * 64) * QKV_N + h * HD;

    #pragma unroll
    for (int i = 0; i < 4; i++) {
        int idx = i * 256 + tid;
        int r = idx >> 4, c4 = (idx & 15) << 2;
        {
            float4 v = *(const float4*)(base + (size_t)r * QKV_N + c4);
            __nv_bfloat16 h0,h1,h2,h3,l0,l1,l2,l3;
            split_bf16(v.x,h0,l0); split_bf16(v.y,h1,l1);
            split_bf16(v.z,h2,l2); split_bf16(v.w,h3,l3);
            __nv_bfloat162 hA = __halves2bfloat162(h0,h1), hB = __halves2bfloat162(h2,h3);
            __nv_bfloat162 lA = __halves2bfloat162(l0,l1), lB = __halves2bfloat162(l2,l3);
            __nv_bfloat16* o = qs + ((size_t)bh * SEQ + st * 64 + r) * HD3 + c4;
            *(__nv_bfloat162*)(o)       = hA; *(__nv_bfloat162*)(o + 2)       = hB;
            *(__nv_bfloat162*)(o + 64)  = hA; *(__nv_bfloat162*)(o + 66)      = hB;
            *(__nv_bfloat162*)(o + 128) = lA; *(__nv_bfloat162*)(o + 130)     = lB;
        }
        {
            float4 v = *(const float4*)(base + DM + (size_t)r * QKV_N + c4);
            __nv_bfloat16 h0,h1,h2,h3,l0,l1,l2,l3;
            split_bf16(v.x,h0,l0); split_bf16(v.y,h1,l1);
            split_bf16(v.z,h2,l2); split_bf16(v.w,h3,l3);
            __nv_bfloat162 hA = __halves2bfloat162(h0,h1), hB = __halves2bfloat162(h2,h3);
            __nv_bfloat162 lA = __halves2bfloat162(l0,l1), lB = __halves2bfloat162(l2,l3);
            __nv_bfloat16* o = ks + ((size_t)bh * SEQ + st * 64 + r) * HD3 + c4;
            *(__nv_bfloat162*)(o)       = hA; *(__nv_bfloat162*)(o + 2)       = hB;
            *(__nv_bfloat162*)(o + 64)  = lA; *(__nv_bfloat162*)(o + 66)      = lB;
            *(__nv_bfloat162*)(o + 128) = hA; *(__nv_bfloat162*)(o + 130)     = hB;
        }
        float4 v = *(const float4*)(base + 2 * DM + (size_t)r * QKV_N + c4);
        vs[r][c4] = v.x; vs[r][c4+1] = v.y; vs[r][c4+2] = v.z; vs[r][c4+3] = v.w;
    }
    __syncthreads();
    #pragma unroll
    for (int i = 0; i < 4; i++) {
        int idx = i * 256 + tid;
        int d = idx >> 4, s4 = (idx & 15) << 2;
        float x0 = vs[s4][d], x1 = vs[s4+1][d], x2 = vs[s4+2][d], x3 = vs[s4+3][d];
        __nv_bfloat16 h0,h1,h2,h3,l0,l1,l2,l3;
        split_bf16(x0,h0,l0); split_bf16(x1,h1,l1);
        split_bf16(x2,h2,l2); split_bf16(x3,h3,l3);
        __nv_bfloat16* oh = vth + ((size_t)bh * HD + d) * SEQ + st * 64 + s4;
        __nv_bfloat16* ol = vtl + ((size_t)bh * HD + d) * SEQ + st * 64 + s4;
        *(__nv_bfloat162*)(oh)     = __halves2bfloat162(h0,h1);
        *(__nv_bfloat162*)(oh + 2) = __halves2bfloat162(h2,h3);
        *(__nv_bfloat162*)(ol)     = __halves2bfloat162(l0,l1);
        *(__nv_bfloat162*)(ol + 2) = __halves2bfloat162(l2,l3);
    }
}

// ---------------------------------------------------------------------------
// HMMA split GEMM v2: C[M,N] = A'[M,3072] @ B'[N,3072]^T  (fp32 accumulate)
// BM=BN=128, BK=64; 3-stage cp.async pipeline; XOR-swizzled smem (128B rows,
// chunk ^ (row&7)); ldmatrix.x4 fragment loads. 8 warps (4x2), warp 32x64.
// ---------------------------------------------------------------------------
#define BM 128
#define BN 128
#define BK 64
#define STAGE_B 32768          // (128+128) rows * 128B
#define A_STAGE 16384

__global__ __launch_bounds__(256, 2)
void hmma_split_gemm(const __nv_bfloat16* __restrict__ A,
                     const __nv_bfloat16* __restrict__ B,
                     float* __restrict__ C, int N)
{
    extern __shared__ char gsm[];
    const uint32_t dyn = smem_u32(gsm);

    const int tid  = threadIdx.x;
    const int wid  = tid >> 5, lane = tid & 31;
    const int g    = lane >> 2;
    const int tig  = lane & 3;
    const int wm   = (wid >> 1) << 5;  // 0,32,64,96
    const int wn   = (wid & 1) << 6;   // 0,64

    const int row0 = blockIdx.y * BM, col0 = blockIdx.x * BN;
    const char* Ab = (const char*)(A + (size_t)row0 * KSPLIT);
    const char* Bb = (const char*)(B + (size_t)col0 * KSPLIT);

    // per-thread load coords: 4 chunks for A, 4 for B
    const int lrr = tid >> 1;                 // shared row pair base: idx>>3 over 4 iters
    (void)lrr;

    float acc[2][8][4];
    #pragma unroll
    for (int mi = 0; mi < 2; mi++)
        #pragma unroll
        for (int ni = 0; ni < 8; ni++)
            #pragma unroll
            for (int q = 0; q < 4; q++) acc[mi][ni][q] = 0.0f;

    // ldmatrix lane geometry (constant per thread)
    const int lrow = (lane & 7) + (lane & 8);   // 0..15
    const int lchk = lane >> 4;                 // 0/1

#define ISSUE_TILE(stage, kt) do {                                                \
    size_t kb = (size_t)(kt) * (BK * 2);                                          \
    uint32_t sa = dyn + (uint32_t)(stage) * STAGE_B;                              \
    uint32_t sb = sa + A_STAGE;                                                   \
    _Pragma("unroll")                                                             \
    for (int i = 0; i < 4; i++) {                                                 \
        int idx = tid + i * 256;                                                  \
        int rr = idx >> 3, cc = idx & 7;                                          \
        uint32_t soff = (uint32_t)(rr * 8 + (cc ^ (rr & 7))) * 16;                \
        asm volatile("cp.async.cg.shared.global [%0], [%1], 16;"                  \
                     :: "r"(sa + soff),                                           \
                        "l"(Ab + (size_t)rr * (KSPLIT * 2) + kb + cc * 16));      \
        asm volatile("cp.async.cg.shared.global [%0], [%1], 16;"                  \
                     :: "r"(sb + soff),                                           \
                        "l"(Bb + (size_t)rr * (KSPLIT * 2) + kb + cc * 16));      \
    }                                                                             \
    asm volatile("cp.async.commit_group;" ::: "memory");                          \
} while (0)

    const int nk = KSPLIT / BK;   // 48
    ISSUE_TILE(0, 0);
    ISSUE_TILE(1, 1);

    #pragma unroll 1
    for (int kt = 0; kt < nk; kt++) {
        if (kt + 1 < nk) asm volatile("cp.async.wait_group 1;" ::: "memory");
        else             asm volatile("cp.async.wait_group 0;" ::: "memory");
        __syncthreads();

        if (kt + 2 < nk) {
            const int st2 = (kt + 2) % 3;
            ISSUE_TILE(st2, kt + 2);
        }

        const uint32_t sa = dyn + (uint32_t)(kt % 3) * STAGE_B;
        const uint32_t sb = sa + A_STAGE;

        #pragma unroll
        for (int ks = 0; ks < 4; ks++) {
            const int cbase = 2 * ks + lchk;
            uint32_t af[2][4];
            #pragma unroll
            for (int mi = 0; mi < 2; mi++) {
                const int row = wm + mi * 16 + lrow;
                const uint32_t ch = (uint32_t)(cbase ^ (row & 7));
                LDMX4(af[mi], sa + (uint32_t)row * 128 + ch * 16);
            }
            uint32_t bf[4][4];
            #pragma unroll
            for (int np = 0; np < 4; np++) {
                const int row = wn + np * 16 + lrow;
                const uint32_t ch = (uint32_t)(cbase ^ (row & 7));
                LDMX4(bf[np], sb + (uint32_t)row * 128 + ch * 16);
            }
            #pragma unroll
            for (int mi = 0; mi < 2; mi++)
                #pragma unroll
                for (int ni = 0; ni < 8; ni++) {
                    uint32_t bb[2] = { bf[ni >> 1][ni & 1], bf[ni >> 1][(ni & 1) + 2] };
                    MMA_BF16(acc[mi][ni], af[mi], bb);
                }
        }
    }
#undef ISSUE_TILE

    #pragma unroll
    for (int mi = 0; mi < 2; mi++) {
        #pragma unroll
        for (int ni = 0; ni < 8; ni++) {
            int row = row0 + wm + mi * 16 + g;
            int col = col0 + wn + ni * 8 + 2 * tig;
            *(float2*)&C[(size_t)row * N + col] = make_float2(acc[mi][ni][0], acc[mi][ni][1]);
            *(float2*)&C[(size_t)(row + 8) * N + col] = make_float2(acc[mi][ni][2], acc[mi][ni][3]);
        }
    }
}

// ---------------------------------------------------------------------------
// HMMA flash attention (split bf16, causal) — unchanged from round 6.
// ---------------------------------------------------------------------------
#define AST 200

__global__ __launch_bounds__(256, 1)
void hmma_flash_attn(const __nv_bfloat16* __restrict__ qs,
                     const __nv_bfloat16* __restrict__ ks,
                     const __nv_bfloat16* __restrict__ vth,
                     const __nv_bfloat16* __restrict__ vtl,
                     __nv_bfloat16* __restrict__ aout)
{
    extern __shared__ __nv_bfloat16 asm_[];
    __nv_bfloat16* Qs  = asm_;
    __nv_bfloat16* Ks  = asm_ + 128 * AST;
    __nv_bfloat16* Vts = asm_ + 192 * AST;
    __nv_bfloat16* Ps  = asm_ + 256 * AST;

    const int tid  = threadIdx.x;
    const int wid  = tid >> 5, lane = tid & 31;
    const int g    = lane >> 2, tig = lane & 3;
    const int wq0  = wid * 16;

    const int qt = (int)(gridDim.x - 1) - (int)blockIdx.x;
    const int h  = blockIdx.y, b = blockIdx.z;
    const int bh = b * NHEADS + h;
    const int q0 = qt * 128;

    const __nv_bfloat16* qbase = qs  + ((size_t)bh * SEQ + q0) * HD3;
    const __nv_bfloat16* kbase = ks  + (size_t)bh * SEQ * HD3;
    const __nv_bfloat16* vhb   = vth + (size_t)bh * HD * SEQ;
    const __nv_bfloat16* vlb   = vtl + (size_t)bh * HD * SEQ;

    #pragma unroll
    for (int i = 0; i < 12; i++) {
        int idx = i * 256 + tid;
        int r = idx / 24, c = (idx % 24) * 8;
        uint4 v = *(const uint4*)(qbase + (size_t)r * HD3 + c);
        *(uint4*)(Qs + r * AST + c) = v;
    }

    float m0 = -1e30f, m1 = -1e30f, l0 = 0.0f, l1 = 0.0f;
    float o[8][4];
    #pragma unroll
    for (int ni = 0; ni < 8; ni++)
        #pragma unroll
        for (int q = 0; q < 4; q++) o[ni][q] = 0.0f;

    const int nkt = 2 * qt + 2;
    #pragma unroll 1
    for (int kt = 0; kt < nkt; kt++) {
        const int k0 = kt * 64;
        __syncthreads();
        #pragma unroll
        for (int i = 0; i < 6; i++) {
            int idx = i * 256 + tid;
            int r = idx / 24, c = (idx % 24) * 8;
            uint4 v = *(const uint4*)(kbase + (size_t)(k0 + r) * HD3 + c);
            *(uint4*)(Ks + r * AST + c) = v;
        }
        #pragma unroll
        for (int i = 0; i < 2; i++) {
            int idx = i * 256 + tid;
            int d = idx >> 3, s8 = (idx & 7) << 3;
            uint4 vh = *(const uint4*)(vhb + (size_t)d * SEQ + k0 + s8);
            *(uint4*)(Vts + d * AST + s8)       = vh;
            *(uint4*)(Vts + d * AST + 128 + s8) = vh;
            uint4 vl = *(const uint4*)(vlb + (size_t)d * SEQ + k0 + s8);
            *(uint4*)(Vts + d * AST + 64 + s8)  = vl;
        }
        __syncthreads();

        float s[8][4];
        #pragma unroll
        for (int ni = 0; ni < 8; ni++)
            #pragma unroll
            for (int q = 0; q < 4; q++) s[ni][q] = 0.0f;

        #pragma unroll
        for (int kss = 0; kss < 12; kss++) {
            const int kk = kss * 16 + 2 * tig;
            uint32_t a[4];
            const int rA = wq0 + g;
            a[0] = *(const uint32_t*)(Qs + rA * AST + kk);
            a[1] = *(const uint32_t*)(Qs + (rA + 8) * AST + kk);
            a[2] = *(const uint32_t*)(Qs + rA * AST + kk + 8);
            a[3] = *(const uint32_t*)(Qs + (rA + 8) * AST + kk + 8);
            #pragma unroll
            for (int ni = 0; ni < 8; ni++) {
                uint32_t bb[2];
                const int rB = ni * 8 + g;
                bb[0] = *(const uint32_t*)(Ks + rB * AST + kk);
                bb[1] = *(const uint32_t*)(Ks + rB * AST + kk + 8);
                MMA_BF16(s[ni], a, bb);
            }
        }

        const float scale = 0.125f;
        if (kt >= nkt - 2) {
            const int r0 = q0 + wq0 + g, r1 = r0 + 8;
            #pragma unroll
            for (int ni = 0; ni < 8; ni++) {
                const int c = k0 + ni * 8 + 2 * tig;
                s[ni][0] = (c     > r0) ? -1e30f : s[ni][0] * scale;
                s[ni][1] = (c + 1 > r0) ? -1e30f : s[ni][1] * scale;
                s[ni][2] = (c     > r1) ? -1e30f : s[ni][2] * scale;
                s[ni][3] = (c + 1 > r1) ? -1e30f : s[ni][3] * scale;
            }
        } else {
            #pragma unroll
            for (int ni = 0; ni < 8; ni++)
                #pragma unroll
                for (int q = 0; q < 4; q++) s[ni][q] *= scale;
        }

        float rmax0 = -1e30f, rmax1 = -1e30f;
        #pragma unroll
        for (int ni = 0; ni < 8; ni++) {
            rmax0 = fmaxf(rmax0, fmaxf(s[ni][0], s[ni][1]));
            rmax1 = fmaxf(rmax1, fmaxf(s[ni][2], s[ni][3]));
        }
        rmax0 = fmaxf(rmax0, __shfl_xor_sync(0xffffffffu, rmax0, 1));
        rmax0 = fmaxf(rmax0, __shfl_xor_sync(0xffffffffu, rmax0, 2));
        rmax1 = fmaxf(rmax1, __shfl_xor_sync(0xffffffffu, rmax1, 1));
        rmax1 = fmaxf(rmax1, __shfl_xor_sync(0xffffffffu, rmax1, 2));

        const float mn0 = fmaxf(m0, rmax0), mn1 = fmaxf(m1, rmax1);
        const float al0 = __expf(m0 - mn0), al1 = __expf(m1 - mn1);
        float rs0 = 0.0f, rs1 = 0.0f;

        __nv_bfloat16* prow0 = Ps + (wq0 + g) * AST + 2 * tig;
        __nv_bfloat16* prow1 = prow0 + 8 * AST;
        #pragma unroll
        for (int ni = 0; ni < 8; ni++) {
            float p0 = __expf(s[ni][0] - mn0);
            float p1 = __expf(s[ni][1] - mn0);
            float p2 = __expf(s[ni][2] - mn1);
            float p3 = __expf(s[ni][3] - mn1);
            rs0 += p0 + p1; rs1 += p2 + p3;
            __nv_bfloat16 h0,h1,h2,h3,q0b,q1b,q2b,q3b;
            split_bf16(p0,h0,q0b); split_bf16(p1,h1,q1b);
            split_bf16(p2,h2,q2b); split_bf16(p3,h3,q3b);
            __nv_bfloat162 hp01 = __halves2bfloat162(h0,h1);
            __nv_bfloat162 lp01 = __halves2bfloat162(q0b,q1b);
            __nv_bfloat162 hp23 = __halves2bfloat162(h2,h3);
            __nv_bfloat162 lp23 = __halves2bfloat162(q2b,q3b);
            *(__nv_bfloat162*)(prow0 + ni*8)       = hp01;
            *(__nv_bfloat162*)(prow0 + ni*8 + 64)  = hp01;
            *(__nv_bfloat162*)(prow0 + ni*8 + 128) = lp01;
            *(__nv_bfloat162*)(prow1 + ni*8)       = hp23;
            *(__nv_bfloat162*)(prow1 + ni*8 + 64)  = hp23;
            *(__nv_bfloat162*)(prow1 + ni*8 + 128) = lp23;
        }
        rs0 += __shfl_xor_sync(0xffffffffu, rs0, 1);
        rs0 += __shfl_xor_sync(0xffffffffu, rs0, 2);
        rs1 += __shfl_xor_sync(0xffffffffu, rs1, 1);
        rs1 += __shfl_xor_sync(0xffffffffu, rs1, 2);

        l0 = l0 * al0 + rs0; m0 = mn0;
        l1 = l1 * al1 + rs1; m1 = mn1;
        #pragma unroll
        for (int ni = 0; ni < 8; ni++) {
            o[ni][0] *= al0; o[ni][1] *= al0;
            o[ni][2] *= al1; o[ni][3] *= al1;
        }
        __syncwarp();

        #pragma unroll
        for (int kss = 0; kss < 12; kss++) {
            const int kk = kss * 16 + 2 * tig;
            uint32_t a[4];
            const int rA = wq0 + g;
            a[0] = *(const uint32_t*)(Ps + rA * AST + kk);
            a[1] = *(const uint32_t*)(Ps + (rA + 8) * AST + kk);
            a[2] = *(const uint32_t*)(Ps + rA * AST + kk + 8);
            a[3] = *(const uint32_t*)(Ps + (rA + 8) * AST + kk + 8);
            #pragma unroll
            for (int ni = 0; ni < 8; ni++) {
                uint32_t bb[2];
                const int rB = ni * 8 + g;
                bb[0] = *(const uint32_t*)(Vts + rB * AST + kk);
                bb[1] = *(const uint32_t*)(Vts + rB * AST + kk + 8);
                MMA_BF16(o[ni], a, bb);
            }
        }
    }

    const float inv0 = 1.0f / l0, inv1 = 1.0f / l1;
    const size_t t0 = ((size_t)b * SEQ + q0 + wq0 + g) * KSPLIT + h * HD;
    const size_t t1 = t0 + (size_t)8 * KSPLIT;
    #pragma unroll
    for (int ni = 0; ni < 8; ni++) {
        const int c = ni * 8 + 2 * tig;
        float f0 = o[ni][0] * inv0, f1 = o[ni][1] * inv0;
        float f2 = o[ni][2] * inv1, f3 = o[ni][3] * inv1;
        __nv_bfloat16 h0,h1,h2,h3,l0b,l1b,l2b,l3b;
        split_bf16(f0,h0,l0b); split_bf16(f1,h1,l1b);
        split_bf16(f2,h2,l2b); split_bf16(f3,h3,l3b);
        __nv_bfloat162 hp01 = __halves2bfloat162(h0,h1), lp01 = __halves2bfloat162(l0b,l1b);
        __nv_bfloat162 hp23 = __halves2bfloat162(h2,h3), lp23 = __halves2bfloat162(l2b,l3b);
        *(__nv_bfloat162*)(aout + t0 + c)          = hp01;
        *(__nv_bfloat162*)(aout + t0 + DM + c)     = hp01;
        *(__nv_bfloat162*)(aout + t0 + 2*DM + c)   = lp01;
        *(__nv_bfloat162*)(aout + t1 + c)          = hp23;
        *(__nv_bfloat162*)(aout + t1 + DM + c)     = hp23;
        *(__nv_bfloat162*)(aout + t1 + 2*DM + c)   = lp23;
    }
}

// ---------------------------------------------------------------------------
// Launch
// ---------------------------------------------------------------------------
extern "C" void kernel_launch(void* const* d_in, const int* in_sizes, int n_in,
                              void* d_out, int out_size)
{
    const float* x     = (const float*)d_in[0];
    const float* w_qkv = (const float*)d_in[1];
    const float* w_out = (const float*)d_in[2];
    float* out = (float*)d_out;

    float* qkv; cudaGetSymbolAddress((void**)&qkv, g_qkv);
    __nv_bfloat16 *ax, *bqkv, *aattn, *bout, *pqs, *pks, *pvth, *pvtl;
    cudaGetSymbolAddress((void**)&ax,    g_ax);
    cudaGetSymbolAddress((void**)&bqkv,  g_bqkv);
    cudaGetSymbolAddress((void**)&aattn, g_aattn);
    cudaGetSymbolAddress((void**)&bout,  g_bout);
    cudaGetSymbolAddress((void**)&pqs,   g_qs);
    cudaGetSymbolAddress((void**)&pks,   g_ks);
    cudaGetSymbolAddress((void**)&pvth,  g_vth);
    cudaGetSymbolAddress((void**)&pvtl,  g_vtl);

    const int gemm_smem = 3 * STAGE_B;   // 98304
    cudaFuncSetAttribute(hmma_split_gemm,
                         cudaFuncAttributeMaxDynamicSharedMemorySize, gemm_smem);
    const int fa_smem = 384 * AST * (int)sizeof(__nv_bfloat16);   // 153600 B
    cudaFuncSetAttribute(hmma_flash_attn,
                         cudaFuncAttributeMaxDynamicSharedMemorySize, fa_smem);

    // 1) input splits
    conv_split_kernel<<<TOKENS, 256>>>(x, ax);
    conv_wT_kernel<<<dim3(QKV_N / 32, DM / 32), 256>>>(w_qkv, bqkv, QKV_N);

    // 2) QKV projection (fp32 out)
    hmma_split_gemm<<<dim3(QKV_N / BN, TOKENS / BM), 256, gemm_smem>>>(ax, bqkv, qkv, QKV_N);

    // 3) qkv -> attention split layouts
    conv_qkv_split<<<dim3(SEQ / 64, NHEADS, BATCH), 256>>>(qkv, pqs, pks, pvth, pvtl);

    // 4) HMMA flash attention -> split bf16 activations for out-proj
    hmma_flash_attn<<<dim3(SEQ / 128, NHEADS, BATCH), 256, fa_smem>>>(pqs, pks, pvth, pvtl, aattn);

    // 5) output projection
    conv_wT_kernel<<<dim3(DM / 32, DM / 32), 256>>>(w_out, bout, DM);
    hmma_split_gemm<<<dim3(DM / BN, TOKENS / BM), 256, gemm_smem>>>(aattn, bout, out, DM);
}

// round 8
// speedup vs baseline: 4.0839x; 1.7560x over previous
#include <cuda_runtime.h>
#include <cuda_fp16.h>
#include <cstdint>

// Problem constants
#define BATCH   4
#define SEQ     2048
#define DM      1024
#define NHEADS  16
#define HD      64
#define TOKENS  (BATCH * SEQ)          // 8192
#define QKV_N   (3 * DM)               // 3072
#define KDIM    1024                   // GEMM K (no split)
#define BH      (BATCH * NHEADS)       // 64

// Scratch (device globals — no allocation allowed)
__device__ __half g_xh  [(size_t)TOKENS * DM];     // x fp16
__device__ __half g_wqkv[(size_t)QKV_N * DM];      // w_qkv^T fp16 [N][K]
__device__ __half g_wout[(size_t)DM * DM];         // w_out^T fp16 [N][K]
__device__ __half g_qkvh[(size_t)TOKENS * QKV_N];  // qkv fp16
__device__ __half g_ao  [(size_t)TOKENS * DM];     // attention out fp16
__device__ __half g_q   [(size_t)BH * SEQ * HD];   // Q [bh][s][d]
__device__ __half g_k   [(size_t)BH * SEQ * HD];   // K [bh][s][d]
__device__ __half g_vt  [(size_t)BH * HD * SEQ];   // V^T [bh][d][s]

// ---------------------------------------------------------------------------
// Helpers
// ---------------------------------------------------------------------------
__device__ __forceinline__ uint32_t smem_u32(const void* p) {
    uint32_t a;
    asm("{ .reg .u64 t; cvta.to.shared.u64 t, %1; cvt.u32.u64 %0, t; }" : "=r"(a) : "l"(p));
    return a;
}
#define MMA_F16(d, a, b) \
    asm volatile("mma.sync.aligned.m16n8k16.row.col.f32.f16.f16.f32 " \
        "{%0,%1,%2,%3}, {%4,%5,%6,%7}, {%8,%9}, {%0,%1,%2,%3};" \
        : "+f"((d)[0]), "+f"((d)[1]), "+f"((d)[2]), "+f"((d)[3]) \
        : "r"((a)[0]), "r"((a)[1]), "r"((a)[2]), "r"((a)[3]), \
          "r"((b)[0]), "r"((b)[1]))
#define LDMX4(r, addr) \
    asm volatile("ldmatrix.sync.aligned.m8n8.x4.shared.b16 {%0,%1,%2,%3}, [%4];" \
        : "=r"((r)[0]), "=r"((r)[1]), "=r"((r)[2]), "=r"((r)[3]) : "r"(addr))

// ---------------------------------------------------------------------------
// Conversions
// ---------------------------------------------------------------------------
// fp32 [M*1024] -> fp16, 4 elems/thread
__global__ __launch_bounds__(256)
void conv_f16(const float* __restrict__ in, __half* __restrict__ out)
{
    size_t t = (size_t)blockIdx.x * 256 + threadIdx.x;
    float4 v = *(const float4*)&in[t * 4];
    *(__half2*)&out[t * 4]     = __floats2half2_rn(v.x, v.y);
    *(__half2*)&out[t * 4 + 2] = __floats2half2_rn(v.z, v.w);
}

// w fp32 [1024(K), N] -> out fp16 [N, 1024] (transposed)
__global__ __launch_bounds__(256)
void conv_wT_f16(const float* __restrict__ w, __half* __restrict__ out, int N)
{
    __shared__ float s[32][33];
    int tx = threadIdx.x & 31, ty = threadIdx.x >> 5;
    int n0 = blockIdx.x * 32, k0 = blockIdx.y * 32;
    #pragma unroll
    for (int i = 0; i < 4; i++)
        s[ty + 8*i][tx] = w[(size_t)(k0 + ty + 8*i) * N + n0 + tx];
    __syncthreads();
    #pragma unroll
    for (int i = 0; i < 4; i++) {
        int n = n0 + ty + 8*i;
        out[(size_t)n * KDIM + k0 + tx] = __float2half_rn(s[tx][ty + 8*i]);
    }
}

// qkv fp16 [b,s,3072] -> Q/K [bh][s][64] (copy), V^T [bh][d][s] (transpose)
__global__ __launch_bounds__(256)
void conv_qkv_f16(const __half* __restrict__ qkv,
                  __half* __restrict__ q, __half* __restrict__ k,
                  __half* __restrict__ vt)
{
    __shared__ __half vs[64][72];
    const int st = blockIdx.x, h = blockIdx.y, b = blockIdx.z;
    const int bh = b * NHEADS + h;
    const int tid = threadIdx.x;
    const __half* base = qkv + ((size_t)(b * SEQ + st * 64)) * QKV_N + h * HD;

    #pragma unroll
    for (int i = 0; i < 2; i++) {
        int idx = i * 256 + tid;
        int r = idx >> 3, c8 = (idx & 7) << 3;
        uint4 vq = *(const uint4*)(base + (size_t)r * QKV_N + c8);
        *(uint4*)(q + ((size_t)bh * SEQ + st * 64 + r) * HD + c8) = vq;
        uint4 vk = *(const uint4*)(base + DM + (size_t)r * QKV_N + c8);
        *(uint4*)(k + ((size_t)bh * SEQ + st * 64 + r) * HD + c8) = vk;
        uint4 vv = *(const uint4*)(base + 2 * DM + (size_t)r * QKV_N + c8);
        *(uint4*)(&vs[r][c8]) = vv;
    }
    __syncthreads();
    #pragma unroll
    for (int i = 0; i < 2; i++) {
        int idx = i * 256 + tid;
        int d = idx >> 3, s8 = (idx & 7) << 3;
        __half tmp[8];
        #pragma unroll
        for (int j = 0; j < 8; j++) tmp[j] = vs[s8 + j][d];
        *(uint4*)(vt + ((size_t)bh * HD + d) * SEQ + st * 64 + s8) = *(uint4*)tmp;
    }
}

// ---------------------------------------------------------------------------
// HMMA fp16 GEMM: C[M,N] = A[M,1024] @ B[N,1024]^T (fp32 accumulate).
// BM=BN=128, BK=64; 3-stage cp.async; XOR-swizzled smem; ldmatrix.x4.
// half_out: write fp16 C (for qkv) vs fp32 C (final output).
// ---------------------------------------------------------------------------
#define BM 128
#define BN 128
#define BK 64
#define STAGE_B 32768
#define A_STAGE 16384

__global__ __launch_bounds__(256, 2)
void hmma_gemm_f16(const __half* __restrict__ A, const __half* __restrict__ B,
                   void* __restrict__ Cv, int N, int half_out)
{
    extern __shared__ char gsm[];
    const uint32_t dyn = smem_u32(gsm);

    const int tid  = threadIdx.x;
    const int wid  = tid >> 5, lane = tid & 31;
    const int g    = lane >> 2;
    const int tig  = lane & 3;
    const int wm   = (wid >> 1) << 5;
    const int wn   = (wid & 1) << 6;

    const int row0 = blockIdx.y * BM, col0 = blockIdx.x * BN;
    const char* Ab = (const char*)(A + (size_t)row0 * KDIM);
    const char* Bb = (const char*)(B + (size_t)col0 * KDIM);

    float acc[2][8][4];
    #pragma unroll
    for (int mi = 0; mi < 2; mi++)
        #pragma unroll
        for (int ni = 0; ni < 8; ni++)
            #pragma unroll
            for (int q = 0; q < 4; q++) acc[mi][ni][q] = 0.0f;

    const int lrow = (lane & 7) + (lane & 8);
    const int lchk = lane >> 4;

#define ISSUE_TILE(stage, kt) do {                                                \
    size_t kb = (size_t)(kt) * (BK * 2);                                          \
    uint32_t sa = dyn + (uint32_t)(stage) * STAGE_B;                              \
    uint32_t sb = sa + A_STAGE;                                                   \
    _Pragma("unroll")                                                             \
    for (int i = 0; i < 4; i++) {                                                 \
        int idx = tid + i * 256;                                                  \
        int rr = idx >> 3, cc = idx & 7;                                          \
        uint32_t soff = (uint32_t)(rr * 8 + (cc ^ (rr & 7))) * 16;                \
        asm volatile("cp.async.cg.shared.global [%0], [%1], 16;"                  \
                     :: "r"(sa + soff),                                           \
                        "l"(Ab + (size_t)rr * (KDIM * 2) + kb + cc * 16));        \
        asm volatile("cp.async.cg.shared.global [%0], [%1], 16;"                  \
                     :: "r"(sb + soff),                                           \
                        "l"(Bb + (size_t)rr * (KDIM * 2) + kb + cc * 16));        \
    }                                                                             \
    asm volatile("cp.async.commit_group;" ::: "memory");                          \
} while (0)

    const int nk = KDIM / BK;   // 16
    ISSUE_TILE(0, 0);
    ISSUE_TILE(1, 1);

    #pragma unroll 1
    for (int kt = 0; kt < nk; kt++) {
        if (kt + 1 < nk) asm volatile("cp.async.wait_group 1;" ::: "memory");
        else             asm volatile("cp.async.wait_group 0;" ::: "memory");
        __syncthreads();

        if (kt + 2 < nk) {
            const int st2 = (kt + 2) % 3;
            ISSUE_TILE(st2, kt + 2);
        }

        const uint32_t sa = dyn + (uint32_t)(kt % 3) * STAGE_B;
        const uint32_t sb = sa + A_STAGE;

        #pragma unroll
        for (int ks = 0; ks < 4; ks++) {
            const int cbase = 2 * ks + lchk;
            uint32_t af[2][4];
            #pragma unroll
            for (int mi = 0; mi < 2; mi++) {
                const int row = wm + mi * 16 + lrow;
                const uint32_t ch = (uint32_t)(cbase ^ (row & 7));
                LDMX4(af[mi], sa + (uint32_t)row * 128 + ch * 16);
            }
            uint32_t bf[4][4];
            #pragma unroll
            for (int np = 0; np < 4; np++) {
                const int row = wn + np * 16 + lrow;
                const uint32_t ch = (uint32_t)(cbase ^ (row & 7));
                LDMX4(bf[np], sb + (uint32_t)row * 128 + ch * 16);
            }
            #pragma unroll
            for (int mi = 0; mi < 2; mi++)
                #pragma unroll
                for (int ni = 0; ni < 8; ni++) {
                    uint32_t bb[2] = { bf[ni >> 1][ni & 1], bf[ni >> 1][(ni & 1) + 2] };
                    MMA_F16(acc[mi][ni], af[mi], bb);
                }
        }
    }
#undef ISSUE_TILE

    if (half_out) {
        __half* C = (__half*)Cv;
        #pragma unroll
        for (int mi = 0; mi < 2; mi++)
            #pragma unroll
            for (int ni = 0; ni < 8; ni++) {
                int row = row0 + wm + mi * 16 + g;
                int col = col0 + wn + ni * 8 + 2 * tig;
                *(__half2*)&C[(size_t)row * N + col] =
                    __floats2half2_rn(acc[mi][ni][0], acc[mi][ni][1]);
                *(__half2*)&C[(size_t)(row + 8) * N + col] =
                    __floats2half2_rn(acc[mi][ni][2], acc[mi][ni][3]);
            }
    } else {
        float* C = (float*)Cv;
        #pragma unroll
        for (int mi = 0; mi < 2; mi++)
            #pragma unroll
            for (int ni = 0; ni < 8; ni++) {
                int row = row0 + wm + mi * 16 + g;
                int col = col0 + wn + ni * 8 + 2 * tig;
                *(float2*)&C[(size_t)row * N + col] = make_float2(acc[mi][ni][0], acc[mi][ni][1]);
                *(float2*)&C[(size_t)(row + 8) * N + col] = make_float2(acc[mi][ni][2], acc[mi][ni][3]);
            }
    }
}

// ---------------------------------------------------------------------------
// HMMA fp16 flash attention (causal). Block = (b,h,128 q-rows); 8 warps x 16.
// smem 55KB -> 2 CTAs/SM. K'=64 (no split).
// ---------------------------------------------------------------------------
#define AST 72

__global__ __launch_bounds__(256, 2)
void hmma_flash_f16(const __half* __restrict__ qg, const __half* __restrict__ kg,
                    const __half* __restrict__ vtg, __half* __restrict__ ao)
{
    extern __shared__ __half fsm[];
    __half* Qs  = fsm;               // [128][AST]
    __half* Ks  = fsm + 128 * AST;   // [64][AST]
    __half* Vts = fsm + 192 * AST;   // [64][AST]
    __half* Ps  = fsm + 256 * AST;   // [128][AST]

    const int tid  = threadIdx.x;
    const int wid  = tid >> 5, lane = tid & 31;
    const int g    = lane >> 2, tig = lane & 3;
    const int wq0  = wid * 16;

    const int qt = (int)(gridDim.x - 1) - (int)blockIdx.x;  // big tiles first
    const int h  = blockIdx.y, b = blockIdx.z;
    const int bh = b * NHEADS + h;
    const int q0 = qt * 128;

    const __half* qb = qg  + ((size_t)bh * SEQ + q0) * HD;
    const __half* kb = kg  + (size_t)bh * SEQ * HD;
    const __half* vb = vtg + (size_t)bh * HD * SEQ;

    // load Q [128][64]
    #pragma unroll
    for (int i = 0; i < 4; i++) {
        int idx = i * 256 + tid;
        int r = idx >> 3, c = (idx & 7) << 3;
        uint4 v = *(const uint4*)(qb + (size_t)r * HD + c);
        *(uint4*)(Qs + r * AST + c) = v;
    }

    float m0 = -1e30f, m1 = -1e30f, l0 = 0.0f, l1 = 0.0f;
    float o[8][4];
    #pragma unroll
    for (int ni = 0; ni < 8; ni++)
        #pragma unroll
        for (int q = 0; q < 4; q++) o[ni][q] = 0.0f;

    const int nkt = 2 * qt + 2;
    #pragma unroll 1
    for (int kt = 0; kt < nkt; kt++) {
        const int k0 = kt * 64;
        __syncthreads();
        // K tile [64][64], V^T tile [64 d][64 s]
        #pragma unroll
        for (int i = 0; i < 2; i++) {
            int idx = i * 256 + tid;
            int r = idx >> 3, c = (idx & 7) << 3;
            uint4 v = *(const uint4*)(kb + (size_t)(k0 + r) * HD + c);
            *(uint4*)(Ks + r * AST + c) = v;
            uint4 vv = *(const uint4*)(vb + (size_t)r * SEQ + k0 + c);
            *(uint4*)(Vts + r * AST + c) = vv;
        }
        __syncthreads();

        // S = Q @ K^T
        float s[8][4];
        #pragma unroll
        for (int ni = 0; ni < 8; ni++)
            #pragma unroll
            for (int q = 0; q < 4; q++) s[ni][q] = 0.0f;

        #pragma unroll
        for (int kss = 0; kss < 4; kss++) {
            const int kk = kss * 16 + 2 * tig;
            uint32_t a[4];
            const int rA = wq0 + g;
            a[0] = *(const uint32_t*)(Qs + rA * AST + kk);
            a[1] = *(const uint32_t*)(Qs + (rA + 8) * AST + kk);
            a[2] = *(const uint32_t*)(Qs + rA * AST + kk + 8);
            a[3] = *(const uint32_t*)(Qs + (rA + 8) * AST + kk + 8);
            #pragma unroll
            for (int ni = 0; ni < 8; ni++) {
                uint32_t bb[2];
                const int rB = ni * 8 + g;
                bb[0] = *(const uint32_t*)(Ks + rB * AST + kk);
                bb[1] = *(const uint32_t*)(Ks + rB * AST + kk + 8);
                MMA_F16(s[ni], a, bb);
            }
        }

        const float scale = 0.125f;
        if (kt >= nkt - 2) {
            const int r0 = q0 + wq0 + g, r1 = r0 + 8;
            #pragma unroll
            for (int ni = 0; ni < 8; ni++) {
                const int c = k0 + ni * 8 + 2 * tig;
                s[ni][0] = (c     > r0) ? -1e30f : s[ni][0] * scale;
                s[ni][1] = (c + 1 > r0) ? -1e30f : s[ni][1] * scale;
                s[ni][2] = (c     > r1) ? -1e30f : s[ni][2] * scale;
                s[ni][3] = (c + 1 > r1) ? -1e30f : s[ni][3] * scale;
            }
        } else {
            #pragma unroll
            for (int ni = 0; ni < 8; ni++)
                #pragma unroll
                for (int q = 0; q < 4; q++) s[ni][q] *= scale;
        }

        // warp-local online softmax (rows wq0+g, wq0+8+g)
        float rmax0 = -1e30f, rmax1 = -1e30f;
        #pragma unroll
        for (int ni = 0; ni < 8; ni++) {
            rmax0 = fmaxf(rmax0, fmaxf(s[ni][0], s[ni][1]));
            rmax1 = fmaxf(rmax1, fmaxf(s[ni][2], s[ni][3]));
        }
        rmax0 = fmaxf(rmax0, __shfl_xor_sync(0xffffffffu, rmax0, 1));
        rmax0 = fmaxf(rmax0, __shfl_xor_sync(0xffffffffu, rmax0, 2));
        rmax1 = fmaxf(rmax1, __shfl_xor_sync(0xffffffffu, rmax1, 1));
        rmax1 = fmaxf(rmax1, __shfl_xor_sync(0xffffffffu, rmax1, 2));

        const float mn0 = fmaxf(m0, rmax0), mn1 = fmaxf(m1, rmax1);
        const float al0 = __expf(m0 - mn0), al1 = __expf(m1 - mn1);
        float rs0 = 0.0f, rs1 = 0.0f;

        __half* prow0 = Ps + (wq0 + g) * AST + 2 * tig;
        __half* prow1 = prow0 + 8 * AST;
        #pragma unroll
        for (int ni = 0; ni < 8; ni++) {
            float p0 = __expf(s[ni][0] - mn0);
            float p1 = __expf(s[ni][1] - mn0);
            float p2 = __expf(s[ni][2] - mn1);
            float p3 = __expf(s[ni][3] - mn1);
            rs0 += p0 + p1; rs1 += p2 + p3;
            *(__half2*)(prow0 + ni * 8) = __floats2half2_rn(p0, p1);
            *(__half2*)(prow1 + ni * 8) = __floats2half2_rn(p2, p3);
        }
        rs0 += __shfl_xor_sync(0xffffffffu, rs0, 1);
        rs0 += __shfl_xor_sync(0xffffffffu, rs0, 2);
        rs1 += __shfl_xor_sync(0xffffffffu, rs1, 1);
        rs1 += __shfl_xor_sync(0xffffffffu, rs1, 2);

        l0 = l0 * al0 + rs0; m0 = mn0;
        l1 = l1 * al1 + rs1; m1 = mn1;
        #pragma unroll
        for (int ni = 0; ni < 8; ni++) {
            o[ni][0] *= al0; o[ni][1] *= al0;
            o[ni][2] *= al1; o[ni][3] *= al1;
        }
        __syncwarp();

        // O += P @ V  (b from V^T rows = d)
        #pragma unroll
        for (int kss = 0; kss < 4; kss++) {
            const int kk = kss * 16 + 2 * tig;
            uint32_t a[4];
            const int rA = wq0 + g;
            a[0] = *(const uint32_t*)(Ps + rA * AST + kk);
            a[1] = *(const uint32_t*)(Ps + (rA + 8) * AST + kk);
            a[2] = *(const uint32_t*)(Ps + rA * AST + kk + 8);
            a[3] = *(const uint32_t*)(Ps + (rA + 8) * AST + kk + 8);
            #pragma unroll
            for (int ni = 0; ni < 8; ni++) {
                uint32_t bb[2];
                const int rB = ni * 8 + g;
                bb[0] = *(const uint32_t*)(Vts + rB * AST + kk);
                bb[1] = *(const uint32_t*)(Vts + rB * AST + kk + 8);
                MMA_F16(o[ni], a, bb);
            }
        }
    }

    // epilogue: /l, write fp16 [token][DM]
    const float inv0 = 1.0f / l0, inv1 = 1.0f / l1;
    const size_t t0 = ((size_t)b * SEQ + q0 + wq0 + g) * DM + h * HD;
    const size_t t1 = t0 + (size_t)8 * DM;
    #pragma unroll
    for (int ni = 0; ni < 8; ni++) {
        const int c = ni * 8 + 2 * tig;
        *(__half2*)(ao + t0 + c) = __floats2half2_rn(o[ni][0] * inv0, o[ni][1] * inv0);
        *(__half2*)(ao + t1 + c) = __floats2half2_rn(o[ni][2] * inv1, o[ni][3] * inv1);
    }
}

// ---------------------------------------------------------------------------
// Launch
// ---------------------------------------------------------------------------
extern "C" void kernel_launch(void* const* d_in, const int* in_sizes, int n_in,
                              void* d_out, int out_size)
{
    const float* x     = (const float*)d_in[0];
    const float* w_qkv = (const float*)d_in[1];
    const float* w_out = (const float*)d_in[2];
    float* out = (float*)d_out;

    __half *xh, *wqkv, *wout, *qkvh, *ao, *pq, *pk, *pvt;
    cudaGetSymbolAddress((void**)&xh,   g_xh);
    cudaGetSymbolAddress((void**)&wqkv, g_wqkv);
    cudaGetSymbolAddress((void**)&wout, g_wout);
    cudaGetSymbolAddress((void**)&qkvh, g_qkvh);
    cudaGetSymbolAddress((void**)&ao,   g_ao);
    cudaGetSymbolAddress((void**)&pq,   g_q);
    cudaGetSymbolAddress((void**)&pk,   g_k);
    cudaGetSymbolAddress((void**)&pvt,  g_vt);

    const int gemm_smem = 3 * STAGE_B;                         // 98304
    cudaFuncSetAttribute(hmma_gemm_f16,
                         cudaFuncAttributeMaxDynamicSharedMemorySize, gemm_smem);
    const int fa_smem = 384 * AST * (int)sizeof(__half);       // 55296
    cudaFuncSetAttribute(hmma_flash_f16,
                         cudaFuncAttributeMaxDynamicSharedMemorySize, fa_smem);

    // 1) fp32 -> fp16 conversions
    conv_f16<<<TOKENS * DM / 1024, 256>>>(x, xh);
    conv_wT_f16<<<dim3(QKV_N / 32, KDIM / 32), 256>>>(w_qkv, wqkv, QKV_N);
    conv_wT_f16<<<dim3(DM / 32, KDIM / 32), 256>>>(w_out, wout, DM);

    // 2) QKV projection -> fp16 qkv
    hmma_gemm_f16<<<dim3(QKV_N / BN, TOKENS / BM), 256, gemm_smem>>>(xh, wqkv, qkvh, QKV_N, 1);

    // 3) reshape to attention layouts
    conv_qkv_f16<<<dim3(SEQ / 64, NHEADS, BATCH), 256>>>(qkvh, pq, pk, pvt);

    // 4) flash attention -> fp16 activations
    hmma_flash_f16<<<dim3(SEQ / 128, NHEADS, BATCH), 256, fa_smem>>>(pq, pk, pvt, ao);

    // 5) output projection -> fp32 out
    hmma_gemm_f16<<<dim3(DM / BN, TOKENS / BM), 256, gemm_smem>>>(ao, wout, out, DM, 0);
}

// round 9
// speedup vs baseline: 6.7379x; 1.6499x over previous
#include <cuda_runtime.h>
#include <cuda_fp16.h>
#include <cstdint>

// Problem constants
#define BATCH   4
#define SEQ     2048
#define DM      1024
#define NHEADS  16
#define HD      64
#define TOKENS  (BATCH * SEQ)          // 8192
#define QKV_N   (3 * DM)               // 3072
#define KDIM    1024
#define BH      (BATCH * NHEADS)       // 64

// Scratch (device globals — no allocation allowed)
__device__ __half g_xh  [(size_t)TOKENS * DM];     // x fp16
__device__ __half g_wqkv[(size_t)QKV_N * DM];      // w_qkv^T fp16 [N][K]
__device__ __half g_wout[(size_t)DM * DM];         // w_out^T fp16 [N][K]
__device__ __half g_ao  [(size_t)TOKENS * DM];     // attention out fp16
__device__ __half g_q   [(size_t)BH * SEQ * HD];   // Q [bh][s][d]
__device__ __half g_k   [(size_t)BH * SEQ * HD];   // K [bh][s][d]
__device__ __half g_vt  [(size_t)BH * HD * SEQ];   // V^T [bh][d][s]

// ---------------------------------------------------------------------------
// Helpers
// ---------------------------------------------------------------------------
__device__ __forceinline__ uint32_t smem_u32(const void* p) {
    uint32_t a;
    asm("{ .reg .u64 t; cvta.to.shared.u64 t, %1; cvt.u32.u64 %0, t; }" : "=r"(a) : "l"(p));
    return a;
}
#define MMA_F16(d, a, b) \
    asm volatile("mma.sync.aligned.m16n8k16.row.col.f32.f16.f16.f32 " \
        "{%0,%1,%2,%3}, {%4,%5,%6,%7}, {%8,%9}, {%0,%1,%2,%3};" \
        : "+f"((d)[0]), "+f"((d)[1]), "+f"((d)[2]), "+f"((d)[3]) \
        : "r"((a)[0]), "r"((a)[1]), "r"((a)[2]), "r"((a)[3]), \
          "r"((b)[0]), "r"((b)[1]))
#define LDMX4(r, addr) \
    asm volatile("ldmatrix.sync.aligned.m8n8.x4.shared.b16 {%0,%1,%2,%3}, [%4];" \
        : "=r"((r)[0]), "=r"((r)[1]), "=r"((r)[2]), "=r"((r)[3]) : "r"(addr))
#define CP16(dst, src) \
    asm volatile("cp.async.cg.shared.global [%0], [%1], 16;" :: "r"(dst), "l"(src))
#define CP_COMMIT() asm volatile("cp.async.commit_group;" ::: "memory")
#define CP_WAIT(n)  asm volatile("cp.async.wait_group %0;" :: "n"(n) : "memory")

// ---------------------------------------------------------------------------
// Conversions
// ---------------------------------------------------------------------------
__global__ __launch_bounds__(256)
void conv_f16(const float* __restrict__ in, __half* __restrict__ out)
{
    size_t t = (size_t)blockIdx.x * 256 + threadIdx.x;
    float4 v = *(const float4*)&in[t * 4];
    *(__half2*)&out[t * 4]     = __floats2half2_rn(v.x, v.y);
    *(__half2*)&out[t * 4 + 2] = __floats2half2_rn(v.z, v.w);
}

__global__ __launch_bounds__(256)
void conv_wT_f16(const float* __restrict__ w, __half* __restrict__ out, int N)
{
    __shared__ float s[32][33];
    int tx = threadIdx.x & 31, ty = threadIdx.x >> 5;
    int n0 = blockIdx.x * 32, k0 = blockIdx.y * 32;
    #pragma unroll
    for (int i = 0; i < 4; i++)
        s[ty + 8*i][tx] = w[(size_t)(k0 + ty + 8*i) * N + n0 + tx];
    __syncthreads();
    #pragma unroll
    for (int i = 0; i < 4; i++) {
        int n = n0 + ty + 8*i;
        out[(size_t)n * KDIM + k0 + tx] = __float2half_rn(s[tx][ty + 8*i]);
    }
}

// ---------------------------------------------------------------------------
// HMMA fp16 GEMM: C = A[M,1024] @ B[N,1024]^T, fp32 accum.
// mode 0: fp32 C (out-projection).  mode 1: fused QKV epilogue -> g_q/g_k/g_vt.
// ---------------------------------------------------------------------------
#define BM 128
#define BN 128
#define BK 64
#define STAGE_B 32768
#define A_STAGE 16384

__global__ __launch_bounds__(256, 2)
void hmma_gemm_f16(const __half* __restrict__ A, const __half* __restrict__ B,
                   void* __restrict__ Cv, int N, int mode)
{
    extern __shared__ char gsm[];
    const uint32_t dyn = smem_u32(gsm);

    const int tid  = threadIdx.x;
    const int wid  = tid >> 5, lane = tid & 31;
    const int g    = lane >> 2;
    const int tig  = lane & 3;
    const int wm   = (wid >> 1) << 5;
    const int wn   = (wid & 1) << 6;

    const int row0 = blockIdx.y * BM, col0 = blockIdx.x * BN;
    const char* Ab = (const char*)(A + (size_t)row0 * KDIM);
    const char* Bb = (const char*)(B + (size_t)col0 * KDIM);

    float acc[2][8][4];
    #pragma unroll
    for (int mi = 0; mi < 2; mi++)
        #pragma unroll
        for (int ni = 0; ni < 8; ni++)
            #pragma unroll
            for (int q = 0; q < 4; q++) acc[mi][ni][q] = 0.0f;

    const int lrow = (lane & 7) + (lane & 8);
    const int lchk = lane >> 4;

#define ISSUE_TILE(stage, kt) do {                                                \
    size_t kb = (size_t)(kt) * (BK * 2);                                          \
    uint32_t sa = dyn + (uint32_t)(stage) * STAGE_B;                              \
    uint32_t sb = sa + A_STAGE;                                                   \
    _Pragma("unroll")                                                             \
    for (int i = 0; i < 4; i++) {                                                 \
        int idx = tid + i * 256;                                                  \
        int rr = idx >> 3, cc = idx & 7;                                          \
        uint32_t soff = (uint32_t)(rr * 8 + (cc ^ (rr & 7))) * 16;                \
        CP16(sa + soff, Ab + (size_t)rr * (KDIM * 2) + kb + cc * 16);             \
        CP16(sb + soff, Bb + (size_t)rr * (KDIM * 2) + kb + cc * 16);             \
    }                                                                             \
    CP_COMMIT();                                                                  \
} while (0)

    const int nk = KDIM / BK;   // 16
    ISSUE_TILE(0, 0);
    ISSUE_TILE(1, 1);

    #pragma unroll 1
    for (int kt = 0; kt < nk; kt++) {
        if (kt + 1 < nk) CP_WAIT(1);
        else             CP_WAIT(0);
        __syncthreads();

        if (kt + 2 < nk) ISSUE_TILE((kt + 2) % 3, kt + 2);

        const uint32_t sa = dyn + (uint32_t)(kt % 3) * STAGE_B;
        const uint32_t sb = sa + A_STAGE;

        #pragma unroll
        for (int ks = 0; ks < 4; ks++) {
            const int cbase = 2 * ks + lchk;
            uint32_t af[2][4];
            #pragma unroll
            for (int mi = 0; mi < 2; mi++) {
                const int row = wm + mi * 16 + lrow;
                const uint32_t ch = (uint32_t)(cbase ^ (row & 7));
                LDMX4(af[mi], sa + (uint32_t)row * 128 + ch * 16);
            }
            uint32_t bf[4][4];
            #pragma unroll
            for (int np = 0; np < 4; np++) {
                const int row = wn + np * 16 + lrow;
                const uint32_t ch = (uint32_t)(cbase ^ (row & 7));
                LDMX4(bf[np], sb + (uint32_t)row * 128 + ch * 16);
            }
            #pragma unroll
            for (int mi = 0; mi < 2; mi++)
                #pragma unroll
                for (int ni = 0; ni < 8; ni++) {
                    uint32_t bb[2] = { bf[ni >> 1][ni & 1], bf[ni >> 1][(ni & 1) + 2] };
                    MMA_F16(acc[mi][ni], af[mi], bb);
                }
        }
    }
#undef ISSUE_TILE

    if (mode == 0) {
        float* C = (float*)Cv;
        #pragma unroll
        for (int mi = 0; mi < 2; mi++)
            #pragma unroll
            for (int ni = 0; ni < 8; ni++) {
                int row = row0 + wm + mi * 16 + g;
                int col = col0 + wn + ni * 8 + 2 * tig;
                *(float2*)&C[(size_t)row * N + col] = make_float2(acc[mi][ni][0], acc[mi][ni][1]);
                *(float2*)&C[(size_t)(row + 8) * N + col] = make_float2(acc[mi][ni][2], acc[mi][ni][3]);
            }
    } else {
        // fused QKV epilogue: block's 128 cols lie in exactly one of Q/K/V
        const int sec = (col0 + wn) >> 10;     // 0=Q, 1=K, 2=V
        #pragma unroll
        for (int mi = 0; mi < 2; mi++) {
            #pragma unroll
            for (int ni = 0; ni < 8; ni++) {
                const int col = col0 + wn + ni * 8 + 2 * tig;
                const int cc  = col & 1023;
                const int h   = cc >> 6, d = cc & 63;
                #pragma unroll
                for (int half_i = 0; half_i < 2; half_i++) {
                    const int r = row0 + wm + mi * 16 + g + half_i * 8;
                    const int b = r >> 11, s = r & 2047;
                    const size_t bh = (size_t)(b * NHEADS + h);
                    const float a0 = acc[mi][ni][half_i * 2];
                    const float a1 = acc[mi][ni][half_i * 2 + 1];
                    if (sec == 0) {
                        *(__half2*)&g_q[(bh * SEQ + s) * HD + d] = __floats2half2_rn(a0, a1);
                    } else if (sec == 1) {
                        *(__half2*)&g_k[(bh * SEQ + s) * HD + d] = __floats2half2_rn(a0, a1);
                    } else {
                        g_vt[(bh * HD + d)     * SEQ + s] = __float2half_rn(a0);
                        g_vt[(bh * HD + d + 1) * SEQ + s] = __float2half_rn(a1);
                    }
                }
            }
        }
    }
}

// ---------------------------------------------------------------------------
// HMMA fp16 flash attention (causal), cp.async double-buffered K/V.
// Block = (b,h,128 q-rows); 8 warps x 16 rows; one __syncthreads per k-tile.
// ---------------------------------------------------------------------------
#define AST 72
#define KVB (64 * AST * 2)          // one K or V stage in bytes (9216)
#define FA_SMEM (128*AST*2 + 4*KVB + 128*AST*2)   // Q + 2K + 2V + P = 73728

__global__ __launch_bounds__(256, 2)
void hmma_flash_f16(const __half* __restrict__ qg, const __half* __restrict__ kg,
                    const __half* __restrict__ vtg, __half* __restrict__ ao)
{
    extern __shared__ __half fsm[];
    __half* Qs = fsm;                              // [128][AST]
    __half* Kd = fsm + 128 * AST;                  // [2][64][AST]
    __half* Vd = Kd + 2 * 64 * AST;                // [2][64][AST]
    __half* Ps = Vd + 2 * 64 * AST;                // [128][AST]
    const uint32_t smQ = smem_u32(Qs);
    const uint32_t smK = smem_u32(Kd);
    const uint32_t smV = smem_u32(Vd);

    const int tid  = threadIdx.x;
    const int wid  = tid >> 5, lane = tid & 31;
    const int g    = lane >> 2, tig = lane & 3;
    const int wq0  = wid * 16;

    const int qt = (int)(gridDim.x - 1) - (int)blockIdx.x;  // big tiles first
    const int h  = blockIdx.y, b = blockIdx.z;
    const int bh = b * NHEADS + h;
    const int q0 = qt * 128;

    const char* qb = (const char*)(qg  + ((size_t)bh * SEQ + q0) * HD);
    const char* kb = (const char*)(kg  + (size_t)bh * SEQ * HD);
    const char* vb = (const char*)(vtg + (size_t)bh * HD * SEQ);

#define ISSUE_KV(kt, st) do {                                                     \
    const size_t koff = (size_t)(kt) * 128;   /* 64 keys * 2B */                  \
    _Pragma("unroll")                                                             \
    for (int i = 0; i < 2; i++) {                                                 \
        int idx = i * 256 + tid;                                                  \
        int r = idx >> 3, c = idx & 7;                                            \
        CP16(smK + (uint32_t)(st) * KVB + (uint32_t)(r * 144 + c * 16),           \
             kb + (koff * HD) + (size_t)r * 128 + c * 16);                        \
        CP16(smV + (uint32_t)(st) * KVB + (uint32_t)(r * 144 + c * 16),           \
             vb + (size_t)r * (SEQ * 2) + koff + c * 16);                         \
    }                                                                             \
    CP_COMMIT();                                                                  \
} while (0)

    // prologue: Q tile + KV tile 0 in one group
    #pragma unroll
    for (int i = 0; i < 4; i++) {
        int idx = i * 256 + tid;
        int r = idx >> 3, c = idx & 7;
        CP16(smQ + (uint32_t)(r * 144 + c * 16), qb + (size_t)r * 128 + c * 16);
    }
    ISSUE_KV(0, 0);

    float m0 = -1e30f, m1 = -1e30f, l0 = 0.0f, l1 = 0.0f;
    float o[8][4];
    #pragma unroll
    for (int ni = 0; ni < 8; ni++)
        #pragma unroll
        for (int q = 0; q < 4; q++) o[ni][q] = 0.0f;

    const int nkt = 2 * qt + 2;
    #pragma unroll 1
    for (int kt = 0; kt < nkt; kt++) {
        CP_WAIT(0);
        __syncthreads();
        if (kt + 1 < nkt) ISSUE_KV(kt + 1, (kt + 1) & 1);

        const __half* Kb = Kd + (kt & 1) * 64 * AST;
        const __half* Vb = Vd + (kt & 1) * 64 * AST;
        const int k0 = kt * 64;

        // S = Q @ K^T
        float s[8][4];
        #pragma unroll
        for (int ni = 0; ni < 8; ni++)
            #pragma unroll
            for (int q = 0; q < 4; q++) s[ni][q] = 0.0f;

        #pragma unroll
        for (int kss = 0; kss < 4; kss++) {
            const int kk = kss * 16 + 2 * tig;
            uint32_t a[4];
            const int rA = wq0 + g;
            a[0] = *(const uint32_t*)(Qs + rA * AST + kk);
            a[1] = *(const uint32_t*)(Qs + (rA + 8) * AST + kk);
            a[2] = *(const uint32_t*)(Qs + rA * AST + kk + 8);
            a[3] = *(const uint32_t*)(Qs + (rA + 8) * AST + kk + 8);
            #pragma unroll
            for (int ni = 0; ni < 8; ni++) {
                uint32_t bb[2];
                const int rB = ni * 8 + g;
                bb[0] = *(const uint32_t*)(Kb + rB * AST + kk);
                bb[1] = *(const uint32_t*)(Kb + rB * AST + kk + 8);
                MMA_F16(s[ni], a, bb);
            }
        }

        const float scale = 0.125f;
        if (kt >= nkt - 2) {
            const int r0 = q0 + wq0 + g, r1 = r0 + 8;
            #pragma unroll
            for (int ni = 0; ni < 8; ni++) {
                const int c = k0 + ni * 8 + 2 * tig;
                s[ni][0] = (c     > r0) ? -1e30f : s[ni][0] * scale;
                s[ni][1] = (c + 1 > r0) ? -1e30f : s[ni][1] * scale;
                s[ni][2] = (c     > r1) ? -1e30f : s[ni][2] * scale;
                s[ni][3] = (c + 1 > r1) ? -1e30f : s[ni][3] * scale;
            }
        } else {
            #pragma unroll
            for (int ni = 0; ni < 8; ni++)
                #pragma unroll
                for (int q = 0; q < 4; q++) s[ni][q] *= scale;
        }

        float rmax0 = -1e30f, rmax1 = -1e30f;
        #pragma unroll
        for (int ni = 0; ni < 8; ni++) {
            rmax0 = fmaxf(rmax0, fmaxf(s[ni][0], s[ni][1]));
            rmax1 = fmaxf(rmax1, fmaxf(s[ni][2], s[ni][3]));
        }
        rmax0 = fmaxf(rmax0, __shfl_xor_sync(0xffffffffu, rmax0, 1));
        rmax0 = fmaxf(rmax0, __shfl_xor_sync(0xffffffffu, rmax0, 2));
        rmax1 = fmaxf(rmax1, __shfl_xor_sync(0xffffffffu, rmax1, 1));
        rmax1 = fmaxf(rmax1, __shfl_xor_sync(0xffffffffu, rmax1, 2));

        const float mn0 = fmaxf(m0, rmax0), mn1 = fmaxf(m1, rmax1);
        const float al0 = __expf(m0 - mn0), al1 = __expf(m1 - mn1);
        float rs0 = 0.0f, rs1 = 0.0f;

        __half* prow0 = Ps + (wq0 + g) * AST + 2 * tig;
        __half* prow1 = prow0 + 8 * AST;
        #pragma unroll
        for (int ni = 0; ni < 8; ni++) {
            float p0 = __expf(s[ni][0] - mn0);
            float p1 = __expf(s[ni][1] - mn0);
            float p2 = __expf(s[ni][2] - mn1);
            float p3 = __expf(s[ni][3] - mn1);
            rs0 += p0 + p1; rs1 += p2 + p3;
            *(__half2*)(prow0 + ni * 8) = __floats2half2_rn(p0, p1);
            *(__half2*)(prow1 + ni * 8) = __floats2half2_rn(p2, p3);
        }
        rs0 += __shfl_xor_sync(0xffffffffu, rs0, 1);
        rs0 += __shfl_xor_sync(0xffffffffu, rs0, 2);
        rs1 += __shfl_xor_sync(0xffffffffu, rs1, 1);
        rs1 += __shfl_xor_sync(0xffffffffu, rs1, 2);

        l0 = l0 * al0 + rs0; m0 = mn0;
        l1 = l1 * al1 + rs1; m1 = mn1;
        #pragma unroll
        for (int ni = 0; ni < 8; ni++) {
            o[ni][0] *= al0; o[ni][1] *= al0;
            o[ni][2] *= al1; o[ni][3] *= al1;
        }
        __syncwarp();

        // O += P @ V
        #pragma unroll
        for (int kss = 0; kss < 4; kss++) {
            const int kk = kss * 16 + 2 * tig;
            uint32_t a[4];
            const int rA = wq0 + g;
            a[0] = *(const uint32_t*)(Ps + rA * AST + kk);
            a[1] = *(const uint32_t*)(Ps + (rA + 8) * AST + kk);
            a[2] = *(const uint32_t*)(Ps + rA * AST + kk + 8);
            a[3] = *(const uint32_t*)(Ps + (rA + 8) * AST + kk + 8);
            #pragma unroll
            for (int ni = 0; ni < 8; ni++) {
                uint32_t bb[2];
                const int rB = ni * 8 + g;
                bb[0] = *(const uint32_t*)(Vb + rB * AST + kk);
                bb[1] = *(const uint32_t*)(Vb + rB * AST + kk + 8);
                MMA_F16(o[ni], a, bb);
            }
        }
    }
#undef ISSUE_KV

    // epilogue: /l, fp16 write
    const float inv0 = 1.0f / l0, inv1 = 1.0f / l1;
    const size_t t0 = ((size_t)b * SEQ + q0 + wq0 + g) * DM + h * HD;
    const size_t t1 = t0 + (size_t)8 * DM;
    #pragma unroll
    for (int ni = 0; ni < 8; ni++) {
        const int c = ni * 8 + 2 * tig;
        *(__half2*)(ao + t0 + c) = __floats2half2_rn(o[ni][0] * inv0, o[ni][1] * inv0);
        *(__half2*)(ao + t1 + c) = __floats2half2_rn(o[ni][2] * inv1, o[ni][3] * inv1);
    }
}

// ---------------------------------------------------------------------------
// Launch
// ---------------------------------------------------------------------------
extern "C" void kernel_launch(void* const* d_in, const int* in_sizes, int n_in,
                              void* d_out, int out_size)
{
    const float* x     = (const float*)d_in[0];
    const float* w_qkv = (const float*)d_in[1];
    const float* w_out = (const float*)d_in[2];
    float* out = (float*)d_out;

    __half *xh, *wqkv, *wout, *ao, *pq, *pk, *pvt;
    cudaGetSymbolAddress((void**)&xh,   g_xh);
    cudaGetSymbolAddress((void**)&wqkv, g_wqkv);
    cudaGetSymbolAddress((void**)&wout, g_wout);
    cudaGetSymbolAddress((void**)&ao,   g_ao);
    cudaGetSymbolAddress((void**)&pq,   g_q);
    cudaGetSymbolAddress((void**)&pk,   g_k);
    cudaGetSymbolAddress((void**)&pvt,  g_vt);

    const int gemm_smem = 3 * STAGE_B;   // 98304
    cudaFuncSetAttribute(hmma_gemm_f16,
                         cudaFuncAttributeMaxDynamicSharedMemorySize, gemm_smem);
    cudaFuncSetAttribute(hmma_flash_f16,
                         cudaFuncAttributeMaxDynamicSharedMemorySize, FA_SMEM);

    // 1) fp32 -> fp16 conversions
    conv_f16<<<TOKENS * DM / 1024, 256>>>(x, xh);
    conv_wT_f16<<<dim3(QKV_N / 32, KDIM / 32), 256>>>(w_qkv, wqkv, QKV_N);
    conv_wT_f16<<<dim3(DM / 32, KDIM / 32), 256>>>(w_out, wout, DM);

    // 2) QKV projection with fused scatter into attention layouts
    hmma_gemm_f16<<<dim3(QKV_N / BN, TOKENS / BM), 256, gemm_smem>>>(xh, wqkv, nullptr, QKV_N, 1);

    // 3) flash attention -> fp16 activations
    hmma_flash_f16<<<dim3(SEQ / 128, NHEADS, BATCH), 256, FA_SMEM>>>(pq, pk, pvt, ao);

    // 4) output projection -> fp32 out
    hmma_gemm_f16<<<dim3(DM / BN, TOKENS / BM), 256, gemm_smem>>>(ao, wout, out, DM, 0);
}

// round 10
// speedup vs baseline: 7.0132x; 1.0409x over previous
#include <cuda_runtime.h>
#include <cuda_fp16.h>
#include <cstdint>

// Problem constants
#define BATCH   4
#define SEQ     2048
#define DM      1024
#define NHEADS  16
#define HD      64
#define TOKENS  (BATCH * SEQ)          // 8192
#define QKV_N   (3 * DM)               // 3072
#define KDIM    1024
#define BH      (BATCH * NHEADS)       // 64

// Scratch (device globals — no allocation allowed)
__device__ __half g_xh  [(size_t)TOKENS * DM];     // x fp16
__device__ __half g_wqkv[(size_t)QKV_N * DM];      // w_qkv^T fp16 [N][K]
__device__ __half g_wout[(size_t)DM * DM];         // w_out^T fp16 [N][K]
__device__ __half g_ao  [(size_t)TOKENS * DM];     // attention out fp16
__device__ __half g_q   [(size_t)BH * SEQ * HD];   // Q [bh][s][d]
__device__ __half g_k   [(size_t)BH * SEQ * HD];   // K [bh][s][d]
__device__ __half g_vt  [(size_t)BH * HD * SEQ];   // V^T [bh][d][s]

// ---------------------------------------------------------------------------
// Helpers
// ---------------------------------------------------------------------------
__device__ __forceinline__ uint32_t smem_u32(const void* p) {
    uint32_t a;
    asm("{ .reg .u64 t; cvta.to.shared.u64 t, %1; cvt.u32.u64 %0, t; }" : "=r"(a) : "l"(p));
    return a;
}
#define MMA_F16(d, a, b) \
    asm volatile("mma.sync.aligned.m16n8k16.row.col.f32.f16.f16.f32 " \
        "{%0,%1,%2,%3}, {%4,%5,%6,%7}, {%8,%9}, {%0,%1,%2,%3};" \
        : "+f"((d)[0]), "+f"((d)[1]), "+f"((d)[2]), "+f"((d)[3]) \
        : "r"((a)[0]), "r"((a)[1]), "r"((a)[2]), "r"((a)[3]), \
          "r"((b)[0]), "r"((b)[1]))
#define LDMX4(r, addr) \
    asm volatile("ldmatrix.sync.aligned.m8n8.x4.shared.b16 {%0,%1,%2,%3}, [%4];" \
        : "=r"((r)[0]), "=r"((r)[1]), "=r"((r)[2]), "=r"((r)[3]) : "r"(addr))
#define CP16(dst, src) \
    asm volatile("cp.async.cg.shared.global [%0], [%1], 16;" :: "r"(dst), "l"(src))
#define CP_COMMIT() asm volatile("cp.async.commit_group;" ::: "memory")
#define CP_WAIT(n)  asm volatile("cp.async.wait_group %0;" :: "n"(n) : "memory")

// ---------------------------------------------------------------------------
// Conversions
// ---------------------------------------------------------------------------
__global__ __launch_bounds__(256)
void conv_f16(const float* __restrict__ in, __half* __restrict__ out)
{
    size_t t = (size_t)blockIdx.x * 256 + threadIdx.x;
    float4 v = *(const float4*)&in[t * 4];
    *(__half2*)&out[t * 4]     = __floats2half2_rn(v.x, v.y);
    *(__half2*)&out[t * 4 + 2] = __floats2half2_rn(v.z, v.w);
}

__global__ __launch_bounds__(256)
void conv_wT_f16(const float* __restrict__ w, __half* __restrict__ out, int N)
{
    __shared__ float s[32][33];
    int tx = threadIdx.x & 31, ty = threadIdx.x >> 5;
    int n0 = blockIdx.x * 32, k0 = blockIdx.y * 32;
    #pragma unroll
    for (int i = 0; i < 4; i++)
        s[ty + 8*i][tx] = w[(size_t)(k0 + ty + 8*i) * N + n0 + tx];
    __syncthreads();
    #pragma unroll
    for (int i = 0; i < 4; i++) {
        int n = n0 + ty + 8*i;
        out[(size_t)n * KDIM + k0 + tx] = __float2half_rn(s[tx][ty + 8*i]);
    }
}

// ---------------------------------------------------------------------------
// HMMA fp16 GEMM (unchanged from round 9): C = A[M,1024] @ B[N,1024]^T.
// mode 0: fp32 C.  mode 1: fused QKV scatter epilogue.
// ---------------------------------------------------------------------------
#define BM 128
#define BN 128
#define BK 64
#define STAGE_B 32768
#define A_STAGE 16384

__global__ __launch_bounds__(256, 2)
void hmma_gemm_f16(const __half* __restrict__ A, const __half* __restrict__ B,
                   void* __restrict__ Cv, int N, int mode)
{
    extern __shared__ char gsm[];
    const uint32_t dyn = smem_u32(gsm);

    const int tid  = threadIdx.x;
    const int wid  = tid >> 5, lane = tid & 31;
    const int g    = lane >> 2;
    const int tig  = lane & 3;
    const int wm   = (wid >> 1) << 5;
    const int wn   = (wid & 1) << 6;

    const int row0 = blockIdx.y * BM, col0 = blockIdx.x * BN;
    const char* Ab = (const char*)(A + (size_t)row0 * KDIM);
    const char* Bb = (const char*)(B + (size_t)col0 * KDIM);

    float acc[2][8][4];
    #pragma unroll
    for (int mi = 0; mi < 2; mi++)
        #pragma unroll
        for (int ni = 0; ni < 8; ni++)
            #pragma unroll
            for (int q = 0; q < 4; q++) acc[mi][ni][q] = 0.0f;

    const int lrow = (lane & 7) + (lane & 8);
    const int lchk = lane >> 4;

#define ISSUE_TILE(stage, kt) do {                                                \
    size_t kb = (size_t)(kt) * (BK * 2);                                          \
    uint32_t sa = dyn + (uint32_t)(stage) * STAGE_B;                              \
    uint32_t sb = sa + A_STAGE;                                                   \
    _Pragma("unroll")                                                             \
    for (int i = 0; i < 4; i++) {                                                 \
        int idx = tid + i * 256;                                                  \
        int rr = idx >> 3, cc = idx & 7;                                          \
        uint32_t soff = (uint32_t)(rr * 8 + (cc ^ (rr & 7))) * 16;                \
        CP16(sa + soff, Ab + (size_t)rr * (KDIM * 2) + kb + cc * 16);             \
        CP16(sb + soff, Bb + (size_t)rr * (KDIM * 2) + kb + cc * 16);             \
    }                                                                             \
    CP_COMMIT();                                                                  \
} while (0)

    const int nk = KDIM / BK;   // 16
    ISSUE_TILE(0, 0);
    ISSUE_TILE(1, 1);

    #pragma unroll 1
    for (int kt = 0; kt < nk; kt++) {
        if (kt + 1 < nk) CP_WAIT(1);
        else             CP_WAIT(0);
        __syncthreads();

        if (kt + 2 < nk) ISSUE_TILE((kt + 2) % 3, kt + 2);

        const uint32_t sa = dyn + (uint32_t)(kt % 3) * STAGE_B;
        const uint32_t sb = sa + A_STAGE;

        #pragma unroll
        for (int ks = 0; ks < 4; ks++) {
            const int cbase = 2 * ks + lchk;
            uint32_t af[2][4];
            #pragma unroll
            for (int mi = 0; mi < 2; mi++) {
                const int row = wm + mi * 16 + lrow;
                const uint32_t ch = (uint32_t)(cbase ^ (row & 7));
                LDMX4(af[mi], sa + (uint32_t)row * 128 + ch * 16);
            }
            uint32_t bf[4][4];
            #pragma unroll
            for (int np = 0; np < 4; np++) {
                const int row = wn + np * 16 + lrow;
                const uint32_t ch = (uint32_t)(cbase ^ (row & 7));
                LDMX4(bf[np], sb + (uint32_t)row * 128 + ch * 16);
            }
            #pragma unroll
            for (int mi = 0; mi < 2; mi++)
                #pragma unroll
                for (int ni = 0; ni < 8; ni++) {
                    uint32_t bb[2] = { bf[ni >> 1][ni & 1], bf[ni >> 1][(ni & 1) + 2] };
                    MMA_F16(acc[mi][ni], af[mi], bb);
                }
        }
    }
#undef ISSUE_TILE

    if (mode == 0) {
        float* C = (float*)Cv;
        #pragma unroll
        for (int mi = 0; mi < 2; mi++)
            #pragma unroll
            for (int ni = 0; ni < 8; ni++) {
                int row = row0 + wm + mi * 16 + g;
                int col = col0 + wn + ni * 8 + 2 * tig;
                *(float2*)&C[(size_t)row * N + col] = make_float2(acc[mi][ni][0], acc[mi][ni][1]);
                *(float2*)&C[(size_t)(row + 8) * N + col] = make_float2(acc[mi][ni][2], acc[mi][ni][3]);
            }
    } else {
        const int sec = (col0 + wn) >> 10;     // 0=Q, 1=K, 2=V
        #pragma unroll
        for (int mi = 0; mi < 2; mi++) {
            #pragma unroll
            for (int ni = 0; ni < 8; ni++) {
                const int col = col0 + wn + ni * 8 + 2 * tig;
                const int cc  = col & 1023;
                const int h   = cc >> 6, d = cc & 63;
                #pragma unroll
                for (int half_i = 0; half_i < 2; half_i++) {
                    const int r = row0 + wm + mi * 16 + g + half_i * 8;
                    const int b = r >> 11, s = r & 2047;
                    const size_t bh = (size_t)(b * NHEADS + h);
                    const float a0 = acc[mi][ni][half_i * 2];
                    const float a1 = acc[mi][ni][half_i * 2 + 1];
                    if (sec == 0) {
                        *(__half2*)&g_q[(bh * SEQ + s) * HD + d] = __floats2half2_rn(a0, a1);
                    } else if (sec == 1) {
                        *(__half2*)&g_k[(bh * SEQ + s) * HD + d] = __floats2half2_rn(a0, a1);
                    } else {
                        g_vt[(bh * HD + d)     * SEQ + s] = __float2half_rn(a0);
                        g_vt[(bh * HD + d + 1) * SEQ + s] = __float2half_rn(a1);
                    }
                }
            }
        }
    }
}

// ---------------------------------------------------------------------------
// HMMA fp16 flash attention v3 (causal).
// Q fragments in registers (loaded once); P a-fragments built in registers
// (no smem round trip); K/V b-fragments via ldmatrix.x4 (GEMM pattern);
// cp.async double-buffered K/V; one __syncthreads per k-tile.
// ---------------------------------------------------------------------------
#define ASTB 144                 // padded row stride in bytes (64 halves + 8 pad)
#define KVB  (64 * ASTB)         // one K or V stage (9216 B)
#define FA_SMEM (128 * ASTB + 4 * KVB)   // Q + 2K + 2V = 55296 B

__global__ __launch_bounds__(256, 2)
void hmma_flash_f16(const __half* __restrict__ qg, const __half* __restrict__ kg,
                    const __half* __restrict__ vtg, __half* __restrict__ ao)
{
    extern __shared__ char fsm[];
    const uint32_t smQ = smem_u32(fsm);
    const uint32_t smK = smQ + 128 * ASTB;
    const uint32_t smV = smK + 2 * KVB;

    const int tid  = threadIdx.x;
    const int wid  = tid >> 5, lane = tid & 31;
    const int g    = lane >> 2, tig = lane & 3;
    const int wq0  = wid * 16;

    const int lrow = (lane & 7) + (lane & 8);   // ldmatrix row within 16
    const int lchk = lane >> 4;                 // ldmatrix col half (0/1)

    const int qt = (int)(gridDim.x - 1) - (int)blockIdx.x;  // big tiles first
    const int h  = blockIdx.y, b = blockIdx.z;
    const int bh = b * NHEADS + h;
    const int q0 = qt * 128;

    const char* qb = (const char*)(qg  + ((size_t)bh * SEQ + q0) * HD);
    const char* kb = (const char*)(kg  + (size_t)bh * SEQ * HD);
    const char* vb = (const char*)(vtg + (size_t)bh * HD * SEQ);

#define ISSUE_KV(kt, st) do {                                                     \
    const size_t koff = (size_t)(kt) * 128;   /* 64 keys * 2B */                  \
    _Pragma("unroll")                                                             \
    for (int i = 0; i < 2; i++) {                                                 \
        int idx = i * 256 + tid;                                                  \
        int r = idx >> 3, c = idx & 7;                                            \
        CP16(smK + (uint32_t)(st) * KVB + (uint32_t)(r * ASTB + c * 16),          \
             kb + (koff * HD) + (size_t)r * 128 + c * 16);                        \
        CP16(smV + (uint32_t)(st) * KVB + (uint32_t)(r * ASTB + c * 16),          \
             vb + (size_t)r * (SEQ * 2) + koff + c * 16);                         \
    }                                                                             \
    CP_COMMIT();                                                                  \
} while (0)

    // prologue: Q tile + KV tile 0
    #pragma unroll
    for (int i = 0; i < 4; i++) {
        int idx = i * 256 + tid;
        int r = idx >> 3, c = idx & 7;
        CP16(smQ + (uint32_t)(r * ASTB + c * 16), qb + (size_t)r * 128 + c * 16);
    }
    CP_COMMIT();
    ISSUE_KV(0, 0);
    CP_WAIT(0);
    __syncthreads();

    // Q fragments: loop-invariant per warp, load once
    uint32_t qf[4][4];
    #pragma unroll
    for (int kss = 0; kss < 4; kss++)
        LDMX4(qf[kss], smQ + (uint32_t)((wq0 + lrow) * ASTB + kss * 32 + lchk * 16));

    float m0 = -1e30f, m1 = -1e30f, l0 = 0.0f, l1 = 0.0f;
    float o[8][4];
    #pragma unroll
    for (int ni = 0; ni < 8; ni++)
        #pragma unroll
        for (int q = 0; q < 4; q++) o[ni][q] = 0.0f;

    const int nkt = 2 * qt + 2;
    #pragma unroll 1
    for (int kt = 0; kt < nkt; kt++) {
        if (kt > 0) { CP_WAIT(0); __syncthreads(); }
        if (kt + 1 < nkt) ISSUE_KV(kt + 1, (kt + 1) & 1);

        const uint32_t Kb = smK + (uint32_t)(kt & 1) * KVB;
        const uint32_t Vb = smV + (uint32_t)(kt & 1) * KVB;
        const int k0 = kt * 64;

        // S = Q @ K^T  (K b-frags via ldmatrix.x4, GEMM pattern)
        float s[8][4];
        #pragma unroll
        for (int ni = 0; ni < 8; ni++)
            #pragma unroll
            for (int q = 0; q < 4; q++) s[ni][q] = 0.0f;

        #pragma unroll
        for (int kss = 0; kss < 4; kss++) {
            uint32_t bf[4][4];
            #pragma unroll
            for (int np = 0; np < 4; np++)
                LDMX4(bf[np], Kb + (uint32_t)((np * 16 + lrow) * ASTB + kss * 32 + lchk * 16));
            #pragma unroll
            for (int ni = 0; ni < 8; ni++) {
                uint32_t bb[2] = { bf[ni >> 1][ni & 1], bf[ni >> 1][(ni & 1) + 2] };
                MMA_F16(s[ni], qf[kss], bb);
            }
        }

        const float scale = 0.125f;
        if (kt >= nkt - 2) {
            const int r0 = q0 + wq0 + g, r1 = r0 + 8;
            #pragma unroll
            for (int ni = 0; ni < 8; ni++) {
                const int c = k0 + ni * 8 + 2 * tig;
                s[ni][0] = (c     > r0) ? -1e30f : s[ni][0] * scale;
                s[ni][1] = (c + 1 > r0) ? -1e30f : s[ni][1] * scale;
                s[ni][2] = (c     > r1) ? -1e30f : s[ni][2] * scale;
                s[ni][3] = (c + 1 > r1) ? -1e30f : s[ni][3] * scale;
            }
        } else {
            #pragma unroll
            for (int ni = 0; ni < 8; ni++)
                #pragma unroll
                for (int q = 0; q < 4; q++) s[ni][q] *= scale;
        }

        // warp-local online softmax (rows wq0+g, wq0+8+g)
        float rmax0 = -1e30f, rmax1 = -1e30f;
        #pragma unroll
        for (int ni = 0; ni < 8; ni++) {
            rmax0 = fmaxf(rmax0, fmaxf(s[ni][0], s[ni][1]));
            rmax1 = fmaxf(rmax1, fmaxf(s[ni][2], s[ni][3]));
        }
        rmax0 = fmaxf(rmax0, __shfl_xor_sync(0xffffffffu, rmax0, 1));
        rmax0 = fmaxf(rmax0, __shfl_xor_sync(0xffffffffu, rmax0, 2));
        rmax1 = fmaxf(rmax1, __shfl_xor_sync(0xffffffffu, rmax1, 1));
        rmax1 = fmaxf(rmax1, __shfl_xor_sync(0xffffffffu, rmax1, 2));

        const float mn0 = fmaxf(m0, rmax0), mn1 = fmaxf(m1, rmax1);
        const float al0 = __expf(m0 - mn0), al1 = __expf(m1 - mn1);
        float rs0 = 0.0f, rs1 = 0.0f;

        // exp + build P a-fragments directly in registers (no smem round trip):
        // pf[kss] = { (p[2kss][0],p[2kss][1]), (p[2kss][2],p[2kss][3]),
        //             (p[2kss+1][0],p[2kss+1][1]), (p[2kss+1][2],p[2kss+1][3]) }
        uint32_t pf[4][4];
        #pragma unroll
        for (int ni = 0; ni < 8; ni++) {
            float p0 = __expf(s[ni][0] - mn0);
            float p1 = __expf(s[ni][1] - mn0);
            float p2 = __expf(s[ni][2] - mn1);
            float p3 = __expf(s[ni][3] - mn1);
            rs0 += p0 + p1; rs1 += p2 + p3;
            const int kss = ni >> 1, hi = (ni & 1) << 1;
            __half2 h01 = __floats2half2_rn(p0, p1);
            __half2 h23 = __floats2half2_rn(p2, p3);
            pf[kss][hi]     = *(uint32_t*)&h01;
            pf[kss][hi + 1] = *(uint32_t*)&h23;
        }
        rs0 += __shfl_xor_sync(0xffffffffu, rs0, 1);
        rs0 += __shfl_xor_sync(0xffffffffu, rs0, 2);
        rs1 += __shfl_xor_sync(0xffffffffu, rs1, 1);
        rs1 += __shfl_xor_sync(0xffffffffu, rs1, 2);

        l0 = l0 * al0 + rs0; m0 = mn0;
        l1 = l1 * al1 + rs1; m1 = mn1;
        #pragma unroll
        for (int ni = 0; ni < 8; ni++) {
            o[ni][0] *= al0; o[ni][1] *= al0;
            o[ni][2] *= al1; o[ni][3] *= al1;
        }

        // O += P @ V  (V b-frags via ldmatrix.x4)
        #pragma unroll
        for (int kss = 0; kss < 4; kss++) {
            uint32_t bf[4][4];
            #pragma unroll
            for (int np = 0; np < 4; np++)
                LDMX4(bf[np], Vb + (uint32_t)((np * 16 + lrow) * ASTB + kss * 32 + lchk * 16));
            #pragma unroll
            for (int ni = 0; ni < 8; ni++) {
                uint32_t bb[2] = { bf[ni >> 1][ni & 1], bf[ni >> 1][(ni & 1) + 2] };
                MMA_F16(o[ni], pf[kss], bb);
            }
        }
    }
#undef ISSUE_KV

    // epilogue: /l, fp16 write
    const float inv0 = 1.0f / l0, inv1 = 1.0f / l1;
    const size_t t0 = ((size_t)b * SEQ + q0 + wq0 + g) * DM + h * HD;
    const size_t t1 = t0 + (size_t)8 * DM;
    #pragma unroll
    for (int ni = 0; ni < 8; ni++) {
        const int c = ni * 8 + 2 * tig;
        *(__half2*)(ao + t0 + c) = __floats2half2_rn(o[ni][0] * inv0, o[ni][1] * inv0);
        *(__half2*)(ao + t1 + c) = __floats2half2_rn(o[ni][2] * inv1, o[ni][3] * inv1);
    }
}

// ---------------------------------------------------------------------------
// Launch
// ---------------------------------------------------------------------------
extern "C" void kernel_launch(void* const* d_in, const int* in_sizes, int n_in,
                              void* d_out, int out_size)
{
    const float* x     = (const float*)d_in[0];
    const float* w_qkv = (const float*)d_in[1];
    const float* w_out = (const float*)d_in[2];
    float* out = (float*)d_out;

    __half *xh, *wqkv, *wout, *ao, *pq, *pk, *pvt;
    cudaGetSymbolAddress((void**)&xh,   g_xh);
    cudaGetSymbolAddress((void**)&wqkv, g_wqkv);
    cudaGetSymbolAddress((void**)&wout, g_wout);
    cudaGetSymbolAddress((void**)&ao,   g_ao);
    cudaGetSymbolAddress((void**)&pq,   g_q);
    cudaGetSymbolAddress((void**)&pk,   g_k);
    cudaGetSymbolAddress((void**)&pvt,  g_vt);

    const int gemm_smem = 3 * STAGE_B;   // 98304
    cudaFuncSetAttribute(hmma_gemm_f16,
                         cudaFuncAttributeMaxDynamicSharedMemorySize, gemm_smem);
    cudaFuncSetAttribute(hmma_flash_f16,
                         cudaFuncAttributeMaxDynamicSharedMemorySize, FA_SMEM);

    // 1) fp32 -> fp16 conversions
    conv_f16<<<TOKENS * DM / 1024, 256>>>(x, xh);
    conv_wT_f16<<<dim3(QKV_N / 32, KDIM / 32), 256>>>(w_qkv, wqkv, QKV_N);
    conv_wT_f16<<<dim3(DM / 32, KDIM / 32), 256>>>(w_out, wout, DM);

    // 2) QKV projection with fused scatter into attention layouts
    hmma_gemm_f16<<<dim3(QKV_N / BN, TOKENS / BM), 256, gemm_smem>>>(xh, wqkv, nullptr, QKV_N, 1);

    // 3) flash attention -> fp16 activations
    hmma_flash_f16<<<dim3(SEQ / 128, NHEADS, BATCH), 256, FA_SMEM>>>(pq, pk, pvt, ao);

    // 4) output projection -> fp32 out
    hmma_gemm_f16<<<dim3(DM / BN, TOKENS / BM), 256, gemm_smem>>>(ao, wout, out, DM, 0);
}

// round 11
// speedup vs baseline: 7.1715x; 1.0226x over previous
#include <cuda_runtime.h>
#include <cuda_fp16.h>
#include <cstdint>

// Problem constants
#define BATCH   4
#define SEQ     2048
#define DM      1024
#define NHEADS  16
#define HD      64
#define TOKENS  (BATCH * SEQ)          // 8192
#define QKV_N   (3 * DM)               // 3072
#define KDIM    1024
#define BH      (BATCH * NHEADS)       // 64

// Scratch (device globals — no allocation allowed)
__device__ __half g_xh  [(size_t)TOKENS * DM];     // x fp16
__device__ __half g_wqkv[(size_t)QKV_N * DM];      // w_qkv^T fp16 [N][K]
__device__ __half g_wout[(size_t)DM * DM];         // w_out^T fp16 [N][K]
__device__ __half g_ao  [(size_t)TOKENS * DM];     // attention out fp16
__device__ __half g_q   [(size_t)BH * SEQ * HD];   // Q [bh][s][d]
__device__ __half g_k   [(size_t)BH * SEQ * HD];   // K [bh][s][d]
__device__ __half g_vt  [(size_t)BH * HD * SEQ];   // V^T [bh][d][s]

// ---------------------------------------------------------------------------
// Helpers
// ---------------------------------------------------------------------------
__device__ __forceinline__ uint32_t smem_u32(const void* p) {
    uint32_t a;
    asm("{ .reg .u64 t; cvta.to.shared.u64 t, %1; cvt.u32.u64 %0, t; }" : "=r"(a) : "l"(p));
    return a;
}
__device__ __forceinline__ float ex2f(float x) {
    float y; asm("ex2.approx.ftz.f32 %0, %1;" : "=f"(y) : "f"(x)); return y;
}
#define MMA_F16(d, a, b) \
    asm volatile("mma.sync.aligned.m16n8k16.row.col.f32.f16.f16.f32 " \
        "{%0,%1,%2,%3}, {%4,%5,%6,%7}, {%8,%9}, {%0,%1,%2,%3};" \
        : "+f"((d)[0]), "+f"((d)[1]), "+f"((d)[2]), "+f"((d)[3]) \
        : "r"((a)[0]), "r"((a)[1]), "r"((a)[2]), "r"((a)[3]), \
          "r"((b)[0]), "r"((b)[1]))
#define LDMX4(r, addr) \
    asm volatile("ldmatrix.sync.aligned.m8n8.x4.shared.b16 {%0,%1,%2,%3}, [%4];" \
        : "=r"((r)[0]), "=r"((r)[1]), "=r"((r)[2]), "=r"((r)[3]) : "r"(addr))
#define CP16(dst, src) \
    asm volatile("cp.async.cg.shared.global [%0], [%1], 16;" :: "r"(dst), "l"(src))
#define CP_COMMIT() asm volatile("cp.async.commit_group;" ::: "memory")
#define CP_WAIT(n)  asm volatile("cp.async.wait_group %0;" :: "n"(n) : "memory")

// ---------------------------------------------------------------------------
// Conversions
// ---------------------------------------------------------------------------
__global__ __launch_bounds__(256)
void conv_f16(const float* __restrict__ in, __half* __restrict__ out)
{
    size_t t = (size_t)blockIdx.x * 256 + threadIdx.x;
    float4 v = *(const float4*)&in[t * 4];
    *(__half2*)&out[t * 4]     = __floats2half2_rn(v.x, v.y);
    *(__half2*)&out[t * 4 + 2] = __floats2half2_rn(v.z, v.w);
}

__global__ __launch_bounds__(256)
void conv_wT_f16(const float* __restrict__ w, __half* __restrict__ out, int N)
{
    __shared__ float s[32][33];
    int tx = threadIdx.x & 31, ty = threadIdx.x >> 5;
    int n0 = blockIdx.x * 32, k0 = blockIdx.y * 32;
    #pragma unroll
    for (int i = 0; i < 4; i++)
        s[ty + 8*i][tx] = w[(size_t)(k0 + ty + 8*i) * N + n0 + tx];
    __syncthreads();
    #pragma unroll
    for (int i = 0; i < 4; i++) {
        int n = n0 + ty + 8*i;
        out[(size_t)n * KDIM + k0 + tx] = __float2half_rn(s[tx][ty + 8*i]);
    }
}

// ---------------------------------------------------------------------------
// HMMA fp16 GEMM (unchanged): C = A[M,1024] @ B[N,1024]^T.
// mode 0: fp32 C.  mode 1: fused QKV scatter epilogue.
// ---------------------------------------------------------------------------
#define BM 128
#define BN 128
#define BK 64
#define STAGE_B 32768
#define A_STAGE 16384

__global__ __launch_bounds__(256, 2)
void hmma_gemm_f16(const __half* __restrict__ A, const __half* __restrict__ B,
                   void* __restrict__ Cv, int N, int mode)
{
    extern __shared__ char gsm[];
    const uint32_t dyn = smem_u32(gsm);

    const int tid  = threadIdx.x;
    const int wid  = tid >> 5, lane = tid & 31;
    const int g    = lane >> 2;
    const int tig  = lane & 3;
    const int wm   = (wid >> 1) << 5;
    const int wn   = (wid & 1) << 6;

    const int row0 = blockIdx.y * BM, col0 = blockIdx.x * BN;
    const char* Ab = (const char*)(A + (size_t)row0 * KDIM);
    const char* Bb = (const char*)(B + (size_t)col0 * KDIM);

    float acc[2][8][4];
    #pragma unroll
    for (int mi = 0; mi < 2; mi++)
        #pragma unroll
        for (int ni = 0; ni < 8; ni++)
            #pragma unroll
            for (int q = 0; q < 4; q++) acc[mi][ni][q] = 0.0f;

    const int lrow = (lane & 7) + (lane & 8);
    const int lchk = lane >> 4;

#define ISSUE_TILE(stage, kt) do {                                                \
    size_t kb = (size_t)(kt) * (BK * 2);                                          \
    uint32_t sa = dyn + (uint32_t)(stage) * STAGE_B;                              \
    uint32_t sb = sa + A_STAGE;                                                   \
    _Pragma("unroll")                                                             \
    for (int i = 0; i < 4; i++) {                                                 \
        int idx = tid + i * 256;                                                  \
        int rr = idx >> 3, cc = idx & 7;                                          \
        uint32_t soff = (uint32_t)(rr * 8 + (cc ^ (rr & 7))) * 16;                \
        CP16(sa + soff, Ab + (size_t)rr * (KDIM * 2) + kb + cc * 16);             \
        CP16(sb + soff, Bb + (size_t)rr * (KDIM * 2) + kb + cc * 16);             \
    }                                                                             \
    CP_COMMIT();                                                                  \
} while (0)

    const int nk = KDIM / BK;   // 16
    ISSUE_TILE(0, 0);
    ISSUE_TILE(1, 1);

    #pragma unroll 1
    for (int kt = 0; kt < nk; kt++) {
        if (kt + 1 < nk) CP_WAIT(1);
        else             CP_WAIT(0);
        __syncthreads();

        if (kt + 2 < nk) ISSUE_TILE((kt + 2) % 3, kt + 2);

        const uint32_t sa = dyn + (uint32_t)(kt % 3) * STAGE_B;
        const uint32_t sb = sa + A_STAGE;

        #pragma unroll
        for (int ks = 0; ks < 4; ks++) {
            const int cbase = 2 * ks + lchk;
            uint32_t af[2][4];
            #pragma unroll
            for (int mi = 0; mi < 2; mi++) {
                const int row = wm + mi * 16 + lrow;
                const uint32_t ch = (uint32_t)(cbase ^ (row & 7));
                LDMX4(af[mi], sa + (uint32_t)row * 128 + ch * 16);
            }
            uint32_t bf[4][4];
            #pragma unroll
            for (int np = 0; np < 4; np++) {
                const int row = wn + np * 16 + lrow;
                const uint32_t ch = (uint32_t)(cbase ^ (row & 7));
                LDMX4(bf[np], sb + (uint32_t)row * 128 + ch * 16);
            }
            #pragma unroll
            for (int mi = 0; mi < 2; mi++)
                #pragma unroll
                for (int ni = 0; ni < 8; ni++) {
                    uint32_t bb[2] = { bf[ni >> 1][ni & 1], bf[ni >> 1][(ni & 1) + 2] };
                    MMA_F16(acc[mi][ni], af[mi], bb);
                }
        }
    }
#undef ISSUE_TILE

    if (mode == 0) {
        float* C = (float*)Cv;
        #pragma unroll
        for (int mi = 0; mi < 2; mi++)
            #pragma unroll
            for (int ni = 0; ni < 8; ni++) {
                int row = row0 + wm + mi * 16 + g;
                int col = col0 + wn + ni * 8 + 2 * tig;
                *(float2*)&C[(size_t)row * N + col] = make_float2(acc[mi][ni][0], acc[mi][ni][1]);
                *(float2*)&C[(size_t)(row + 8) * N + col] = make_float2(acc[mi][ni][2], acc[mi][ni][3]);
            }
    } else {
        const int sec = (col0 + wn) >> 10;     // 0=Q, 1=K, 2=V
        #pragma unroll
        for (int mi = 0; mi < 2; mi++) {
            #pragma unroll
            for (int ni = 0; ni < 8; ni++) {
                const int col = col0 + wn + ni * 8 + 2 * tig;
                const int cc  = col & 1023;
                const int h   = cc >> 6, d = cc & 63;
                #pragma unroll
                for (int half_i = 0; half_i < 2; half_i++) {
                    const int r = row0 + wm + mi * 16 + g + half_i * 8;
                    const int b = r >> 11, s = r & 2047;
                    const size_t bh = (size_t)(b * NHEADS + h);
                    const float a0 = acc[mi][ni][half_i * 2];
                    const float a1 = acc[mi][ni][half_i * 2 + 1];
                    if (sec == 0) {
                        *(__half2*)&g_q[(bh * SEQ + s) * HD + d] = __floats2half2_rn(a0, a1);
                    } else if (sec == 1) {
                        *(__half2*)&g_k[(bh * SEQ + s) * HD + d] = __floats2half2_rn(a0, a1);
                    } else {
                        g_vt[(bh * HD + d)     * SEQ + s] = __float2half_rn(a0);
                        g_vt[(bh * HD + d + 1) * SEQ + s] = __float2half_rn(a1);
                    }
                }
            }
        }
    }
}

// ---------------------------------------------------------------------------
// HMMA fp16 flash attention v4 (causal).
// Per-tile order: softmax(kt) -> [wait/sync/prefetch] -> S(kt+1) -> O(kt):
// 64 back-to-back tensor MMAs per tile; pf extracted first so S(kt+1) reuses
// the s registers (regs <=128 -> 2 CTAs/SM for cross-CTA pipe overlap).
// log2-domain softmax (single EX2 per prob). 4-stage K/V cp.async ring.
// Fully-masked diagonal tiles skipped per warp.
// ---------------------------------------------------------------------------
#define ASTB 144                 // padded row stride (128B data + 16B pad)
#define KSTG (64 * ASTB)         // K sub-stage (9216 B)
#define LSTG (2 * KSTG)          // K+V stage (18432 B)
#define FA_SMEM (128 * ASTB + 4 * LSTG)   // Q + 4 stages = 92160 B

__global__ __launch_bounds__(256, 2)
void hmma_flash_f16(const __half* __restrict__ qg, const __half* __restrict__ kg,
                    const __half* __restrict__ vtg, __half* __restrict__ ao)
{
    extern __shared__ char fsm[];
    const uint32_t smQ = smem_u32(fsm);
    const uint32_t smL = smQ + 128 * ASTB;

    const int tid  = threadIdx.x;
    const int wid  = tid >> 5, lane = tid & 31;
    const int g    = lane >> 2, tig = lane & 3;
    const int wq0  = wid * 16;

    const int lrow = (lane & 7) + (lane & 8);   // ldmatrix row within 16
    const int lchk = lane >> 4;                 // ldmatrix col half (0/1)

    const int qt = (int)(gridDim.x - 1) - (int)blockIdx.x;  // big tiles first
    const int h  = blockIdx.y, b = blockIdx.z;
    const int bh = b * NHEADS + h;
    const int q0 = qt * 128;
    const int row_hi = q0 + wq0 + 15;           // max q-row this warp owns

    const char* qb = (const char*)(qg  + ((size_t)bh * SEQ + q0) * HD);
    const char* kb = (const char*)(kg  + (size_t)bh * SEQ * HD);
    const char* vb = (const char*)(vtg + (size_t)bh * HD * SEQ);

#define ISSUE_L(kt) do {                                                          \
    const int st_ = (kt) & 3;                                                     \
    const size_t koff = (size_t)(kt) * 128;   /* 64 keys * 2B */                  \
    const uint32_t kd = smL + (uint32_t)st_ * LSTG;                               \
    const uint32_t vd = kd + KSTG;                                                \
    _Pragma("unroll")                                                             \
    for (int i = 0; i < 2; i++) {                                                 \
        int idx = i * 256 + tid;                                                  \
        int r = idx >> 3, c = idx & 7;                                            \
        CP16(kd + (uint32_t)(r * ASTB + c * 16),                                  \
             kb + (koff * HD) + (size_t)r * 128 + c * 16);                        \
        CP16(vd + (uint32_t)(r * ASTB + c * 16),                                  \
             vb + (size_t)r * (SEQ * 2) + koff + c * 16);                         \
    }                                                                             \
    CP_COMMIT();                                                                  \
} while (0)

#define S_MMA(kt, s) do {                                                         \
    const uint32_t Kb_ = smL + (uint32_t)((kt) & 3) * LSTG;                       \
    _Pragma("unroll")                                                             \
    for (int kss = 0; kss < 4; kss++) {                                           \
        uint32_t bf[4][4];                                                        \
        _Pragma("unroll")                                                         \
        for (int np = 0; np < 4; np++)                                            \
            LDMX4(bf[np], Kb_ + (uint32_t)((np * 16 + lrow) * ASTB                \
                                           + kss * 32 + lchk * 16));              \
        _Pragma("unroll")                                                         \
        for (int ni = 0; ni < 8; ni++) {                                          \
            uint32_t bb[2] = { bf[ni >> 1][ni & 1], bf[ni >> 1][(ni & 1) + 2] };  \
            MMA_F16((s)[ni], qf[kss], bb);                                        \
        }                                                                         \
    }                                                                             \
} while (0)

    // prologue: Q tile + first KV stages
    #pragma unroll
    for (int i = 0; i < 4; i++) {
        int idx = i * 256 + tid;
        int r = idx >> 3, c = idx & 7;
        CP16(smQ + (uint32_t)(r * ASTB + c * 16), qb + (size_t)r * 128 + c * 16);
    }
    CP_COMMIT();

    const int nkt = 2 * qt + 2;
    ISSUE_L(0);
    if (nkt > 1) ISSUE_L(1);
    if (nkt > 2) ISSUE_L(2);
    if (nkt > 2) CP_WAIT(2); else CP_WAIT(1);
    __syncthreads();

    // Q fragments: loop-invariant, registers
    uint32_t qf[4][4];
    #pragma unroll
    for (int kss = 0; kss < 4; kss++)
        LDMX4(qf[kss], smQ + (uint32_t)((wq0 + lrow) * ASTB + kss * 32 + lchk * 16));

    float m0 = -1e30f, m1 = -1e30f, l0 = 0.0f, l1 = 0.0f;
    float o[8][4];
    #pragma unroll
    for (int ni = 0; ni < 8; ni++)
        #pragma unroll
        for (int q = 0; q < 4; q++) o[ni][q] = 0.0f;

    // log2-domain scale: (1/sqrt(64)) * log2(e)
    const float scale2 = 0.125f * 1.44269504089f;

    // S(0) — tile 0 active for all warps
    float s[8][4];
    #pragma unroll
    for (int ni = 0; ni < 8; ni++)
        #pragma unroll
        for (int q = 0; q < 4; q++) s[ni][q] = 0.0f;
    S_MMA(0, s);

    #pragma unroll 1
    for (int kt = 0; kt < nkt; kt++) {
        const int k0 = kt * 64;
        const bool act = (k0 <= row_hi);
        uint32_t pf[4][4];
        float al0 = 1.0f, al1 = 1.0f;

        if (act) {
            // mask + scale (log2 domain)
            if (kt >= nkt - 2) {
                const int r0 = q0 + wq0 + g, r1 = r0 + 8;
                #pragma unroll
                for (int ni = 0; ni < 8; ni++) {
                    const int c = k0 + ni * 8 + 2 * tig;
                    s[ni][0] = (c     > r0) ? -1e30f : s[ni][0] * scale2;
                    s[ni][1] = (c + 1 > r0) ? -1e30f : s[ni][1] * scale2;
                    s[ni][2] = (c     > r1) ? -1e30f : s[ni][2] * scale2;
                    s[ni][3] = (c + 1 > r1) ? -1e30f : s[ni][3] * scale2;
                }
            } else {
                #pragma unroll
                for (int ni = 0; ni < 8; ni++)
                    #pragma unroll
                    for (int q = 0; q < 4; q++) s[ni][q] *= scale2;
            }

            // warp-local online softmax (rows wq0+g, wq0+8+g), base-2
            float rmax0 = -1e30f, rmax1 = -1e30f;
            #pragma unroll
            for (int ni = 0; ni < 8; ni++) {
                rmax0 = fmaxf(rmax0, fmaxf(s[ni][0], s[ni][1]));
                rmax1 = fmaxf(rmax1, fmaxf(s[ni][2], s[ni][3]));
            }
            rmax0 = fmaxf(rmax0, __shfl_xor_sync(0xffffffffu, rmax0, 1));
            rmax0 = fmaxf(rmax0, __shfl_xor_sync(0xffffffffu, rmax0, 2));
            rmax1 = fmaxf(rmax1, __shfl_xor_sync(0xffffffffu, rmax1, 1));
            rmax1 = fmaxf(rmax1, __shfl_xor_sync(0xffffffffu, rmax1, 2));

            const float mn0 = fmaxf(m0, rmax0), mn1 = fmaxf(m1, rmax1);
            al0 = ex2f(m0 - mn0); al1 = ex2f(m1 - mn1);
            float rs0 = 0.0f, rs1 = 0.0f;

            #pragma unroll
            for (int ni = 0; ni < 8; ni++) {
                float p0 = ex2f(s[ni][0] - mn0);
                float p1 = ex2f(s[ni][1] - mn0);
                float p2 = ex2f(s[ni][2] - mn1);
                float p3 = ex2f(s[ni][3] - mn1);
                rs0 += p0 + p1; rs1 += p2 + p3;
                const int kss = ni >> 1, hi = (ni & 1) << 1;
                __half2 h01 = __floats2half2_rn(p0, p1);
                __half2 h23 = __floats2half2_rn(p2, p3);
                pf[kss][hi]     = *(uint32_t*)&h01;
                pf[kss][hi + 1] = *(uint32_t*)&h23;
            }
            rs0 += __shfl_xor_sync(0xffffffffu, rs0, 1);
            rs0 += __shfl_xor_sync(0xffffffffu, rs0, 2);
            rs1 += __shfl_xor_sync(0xffffffffu, rs1, 1);
            rs1 += __shfl_xor_sync(0xffffffffu, rs1, 2);

            l0 = l0 * al0 + rs0; m0 = mn0;
            l1 = l1 * al1 + rs1; m1 = mn1;
        }

        // pipeline turn: finish load kt+1, prefetch kt+3, compute S(kt+1)
        if (kt + 1 < nkt) {
            if (kt + 2 < nkt) CP_WAIT(1);
            else              CP_WAIT(0);
            __syncthreads();
            if (kt + 3 < nkt) ISSUE_L(kt + 3);
            if ((kt + 1) * 64 <= row_hi) {
                #pragma unroll
                for (int ni = 0; ni < 8; ni++)
                    #pragma unroll
                    for (int q = 0; q < 4; q++) s[ni][q] = 0.0f;
                S_MMA(kt + 1, s);
            }
        }

        if (act) {
            // rescale o, then O += P @ V (V stage kt&3, still resident)
            #pragma unroll
            for (int ni = 0; ni < 8; ni++) {
                o[ni][0] *= al0; o[ni][1] *= al0;
                o[ni][2] *= al1; o[ni][3] *= al1;
            }
            const uint32_t Vb = smL + (uint32_t)(kt & 3) * LSTG + KSTG;
            #pragma unroll
            for (int kss = 0; kss < 4; kss++) {
                uint32_t bf[4][4];
                #pragma unroll
                for (int np = 0; np < 4; np++)
                    LDMX4(bf[np], Vb + (uint32_t)((np * 16 + lrow) * ASTB
                                                  + kss * 32 + lchk * 16));
                #pragma unroll
                for (int ni = 0; ni < 8; ni++) {
                    uint32_t bb[2] = { bf[ni >> 1][ni & 1], bf[ni >> 1][(ni & 1) + 2] };
                    MMA_F16(o[ni], pf[kss], bb);
                }
            }
        }
    }
#undef ISSUE_L
#undef S_MMA

    // epilogue: /l, fp16 write
    const float inv0 = 1.0f / l0, inv1 = 1.0f / l1;
    const size_t t0 = ((size_t)b * SEQ + q0 + wq0 + g) * DM + h * HD;
    const size_t t1 = t0 + (size_t)8 * DM;
    #pragma unroll
    for (int ni = 0; ni < 8; ni++) {
        const int c = ni * 8 + 2 * tig;
        *(__half2*)(ao + t0 + c) = __floats2half2_rn(o[ni][0] * inv0, o[ni][1] * inv0);
        *(__half2*)(ao + t1 + c) = __floats2half2_rn(o[ni][2] * inv1, o[ni][3] * inv1);
    }
}

// ---------------------------------------------------------------------------
// Launch
// ---------------------------------------------------------------------------
extern "C" void kernel_launch(void* const* d_in, const int* in_sizes, int n_in,
                              void* d_out, int out_size)
{
    const float* x     = (const float*)d_in[0];
    const float* w_qkv = (const float*)d_in[1];
    const float* w_out = (const float*)d_in[2];
    float* out = (float*)d_out;

    __half *xh, *wqkv, *wout, *ao, *pq, *pk, *pvt;
    cudaGetSymbolAddress((void**)&xh,   g_xh);
    cudaGetSymbolAddress((void**)&wqkv, g_wqkv);
    cudaGetSymbolAddress((void**)&wout, g_wout);
    cudaGetSymbolAddress((void**)&ao,   g_ao);
    cudaGetSymbolAddress((void**)&pq,   g_q);
    cudaGetSymbolAddress((void**)&pk,   g_k);
    cudaGetSymbolAddress((void**)&pvt,  g_vt);

    const int gemm_smem = 3 * STAGE_B;   // 98304
    cudaFuncSetAttribute(hmma_gemm_f16,
                         cudaFuncAttributeMaxDynamicSharedMemorySize, gemm_smem);
    cudaFuncSetAttribute(hmma_flash_f16,
                         cudaFuncAttributeMaxDynamicSharedMemorySize, FA_SMEM);

    // 1) fp32 -> fp16 conversions
    conv_f16<<<TOKENS * DM / 1024, 256>>>(x, xh);
    conv_wT_f16<<<dim3(QKV_N / 32, KDIM / 32), 256>>>(w_qkv, wqkv, QKV_N);
    conv_wT_f16<<<dim3(DM / 32, KDIM / 32), 256>>>(w_out, wout, DM);

    // 2) QKV projection with fused scatter into attention layouts
    hmma_gemm_f16<<<dim3(QKV_N / BN, TOKENS / BM), 256, gemm_smem>>>(xh, wqkv, nullptr, QKV_N, 1);

    // 3) flash attention -> fp16 activations
    hmma_flash_f16<<<dim3(SEQ / 128, NHEADS, BATCH), 256, FA_SMEM>>>(pq, pk, pvt, ao);

    // 4) output projection -> fp32 out
    hmma_gemm_f16<<<dim3(DM / BN, TOKENS / BM), 256, gemm_smem>>>(ao, wout, out, DM, 0);
}